// round 4
// baseline (speedup 1.0000x reference)
#include <cuda_runtime.h>
#include <cstdint>

#define D_MODEL   1024
#define NUM_HEADS 16
#define HEAD_DIM  64
#define B_SZ      4
#define T_SZ      2048
#define M_ROWS    (B_SZ * T_SZ)   // 8192

// Scratch (allocation-free rule: __device__ globals)
__device__ float g_q[(size_t)B_SZ * NUM_HEADS * T_SZ * HEAD_DIM];    // (b,h,t,d)
__device__ float g_k[(size_t)B_SZ * NUM_HEADS * T_SZ * HEAD_DIM];
__device__ float g_v[(size_t)B_SZ * NUM_HEADS * T_SZ * HEAD_DIM];
__device__ float g_attn[(size_t)M_ROWS * D_MODEL];                   // (b*T+t, c)

// ---------------------------------------------------------------------------
// C[M,N] = A[M,K] @ W[N,K]^T   (both operands K-contiguous, row-major)
// BM=BN=128, BK=16, 256 threads, 8x8 per thread in split 4+4 quadrants.
// MODE 0: plain row-major store. MODE 1: scatter to (b,h,t,d).
// ---------------------------------------------------------------------------
template <int MODE>
__global__ __launch_bounds__(256)
void gemm_nt_kernel(const float* __restrict__ A, const float* __restrict__ W,
                    float* __restrict__ C, int M, int N, int K)
{
    __shared__ float Ast[16 * 132];   // Ast[k][m], stride 132
    __shared__ float Bst[16 * 132];   // Bst[k][n]

    const int tid = threadIdx.x;
    const int ty = tid >> 4;          // 0..15
    const int tx = tid & 15;          // 0..15
    const int m0 = blockIdx.y << 7;
    const int n0 = blockIdx.x << 7;

    const float* Ap = A + (size_t)m0 * K;
    const float* Wp = W + (size_t)n0 * K;

    float acc[8][8];
#pragma unroll
    for (int i = 0; i < 8; i++)
#pragma unroll
        for (int j = 0; j < 8; j++) acc[i][j] = 0.f;

    for (int kt = 0; kt < K; kt += 16) {
#pragma unroll
        for (int i = 0; i < 2; i++) {
            int v  = tid + (i << 8);      // 0..511
            int r  = v >> 2;              // 0..127
            int c4 = (v & 3) << 2;        // 0,4,8,12
            float4 av = *(const float4*)(Ap + (size_t)r * K + kt + c4);
            Ast[(c4 + 0) * 132 + r] = av.x;
            Ast[(c4 + 1) * 132 + r] = av.y;
            Ast[(c4 + 2) * 132 + r] = av.z;
            Ast[(c4 + 3) * 132 + r] = av.w;
            float4 bv = *(const float4*)(Wp + (size_t)r * K + kt + c4);
            Bst[(c4 + 0) * 132 + r] = bv.x;
            Bst[(c4 + 1) * 132 + r] = bv.y;
            Bst[(c4 + 2) * 132 + r] = bv.z;
            Bst[(c4 + 3) * 132 + r] = bv.w;
        }
        __syncthreads();

#pragma unroll
        for (int k = 0; k < 16; k++) {
            float a[8], b[8];
            *(float4*)&a[0] = *(const float4*)&Ast[k * 132 + (ty << 2)];
            *(float4*)&a[4] = *(const float4*)&Ast[k * 132 + 64 + (ty << 2)];
            *(float4*)&b[0] = *(const float4*)&Bst[k * 132 + (tx << 2)];
            *(float4*)&b[4] = *(const float4*)&Bst[k * 132 + 64 + (tx << 2)];
#pragma unroll
            for (int i = 0; i < 8; i++)
#pragma unroll
                for (int j = 0; j < 8; j++)
                    acc[i][j] = fmaf(a[i], b[j], acc[i][j]);
        }
        __syncthreads();
    }

    // Epilogue: two row halves x two col halves, float4 stores
#pragma unroll
    for (int hi = 0; hi < 2; hi++) {
#pragma unroll
        for (int ii = 0; ii < 4; ii++) {
            int i = hi * 4 + ii;
            int m = m0 + hi * 64 + (ty << 2) + ii;
#pragma unroll
            for (int hj = 0; hj < 2; hj++) {
                int n = n0 + hj * 64 + (tx << 2);
                float4 val = make_float4(acc[i][hj * 4 + 0], acc[i][hj * 4 + 1],
                                         acc[i][hj * 4 + 2], acc[i][hj * 4 + 3]);
                if (MODE == 0) {
                    *(float4*)&C[(size_t)m * N + n] = val;
                } else {
                    int bb = m >> 11;         // m / T_SZ
                    int t  = m & 2047;
                    int hh = n >> 6;          // n / HEAD_DIM (4-group never crosses)
                    int dd = n & 63;
                    *(float4*)&C[(((size_t)bb * NUM_HEADS + hh) * T_SZ + t) * HEAD_DIM + dd] = val;
                }
            }
        }
    }
}

// ---------------------------------------------------------------------------
// Causal flash attention, fp32. One block = (64 q-rows, head h, batch b).
// Qt/Kt stored k-major (conflict-free compute reads). P aliases the K buffer.
// Each thread: 4 q-rows (ty*4+i) x 4 cols (tx*4+j); row reductions via
// shfl_xor within the 16-lane tx-group.
// ---------------------------------------------------------------------------
__global__ __launch_bounds__(256)
void attn_kernel(const float* __restrict__ Qg, const float* __restrict__ Kg,
                 const float* __restrict__ Vg, float* __restrict__ Og)
{
    __shared__ float Qt[64 * 64];    // Qt[k*64 + row]
    __shared__ float KtPs[64 * 64];  // Kt[k*64 + col]  then  Ps[row*64 + col]
    __shared__ float Vs[64 * 64];    // Vs[j*64 + dd]

    const int tid = threadIdx.x;
    const int ty = tid >> 4;
    const int tx = tid & 15;
    const int q0 = blockIdx.x << 6;
    const int h  = blockIdx.y;
    const int b  = blockIdx.z;

    const size_t base = ((size_t)(b * NUM_HEADS + h)) * T_SZ * HEAD_DIM;
    const float* Qp = Qg + base + (size_t)q0 * HEAD_DIM;

    const float scale = 0.125f;      // 1/sqrt(64)
#pragma unroll
    for (int i = 0; i < 4; i++) {
        int v  = tid + (i << 8);     // 0..1023 float4s
        int r  = v >> 4;             // row 0..63
        int c4 = (v & 15) << 2;      // d 0..60
        float4 qv = *(const float4*)(Qp + r * 64 + c4);
        Qt[(c4 + 0) * 64 + r] = qv.x * scale;
        Qt[(c4 + 1) * 64 + r] = qv.y * scale;
        Qt[(c4 + 2) * 64 + r] = qv.z * scale;
        Qt[(c4 + 3) * 64 + r] = qv.w * scale;
    }

    const float NEG_INF = __int_as_float(0xff800000);
    float mrow[4], lrow[4], acc[4][4];
#pragma unroll
    for (int i = 0; i < 4; i++) {
        mrow[i] = NEG_INF;
        lrow[i] = 0.f;
#pragma unroll
        for (int j = 0; j < 4; j++) acc[i][j] = 0.f;
    }

    const int ntiles = (q0 >> 6) + 1;
    for (int kt = 0; kt < ntiles; kt++) {
        const int k0 = kt << 6;
        const float* Kp = Kg + base + (size_t)k0 * HEAD_DIM;
        const float* Vp = Vg + base + (size_t)k0 * HEAD_DIM;

        __syncthreads();  // prev-iter PV reads of Vs / KtPs complete
#pragma unroll
        for (int i = 0; i < 4; i++) {
            int v  = tid + (i << 8);
            int r  = v >> 4;
            int c4 = (v & 15) << 2;
            float4 kv = *(const float4*)(Kp + r * 64 + c4);
            KtPs[(c4 + 0) * 64 + r] = kv.x;
            KtPs[(c4 + 1) * 64 + r] = kv.y;
            KtPs[(c4 + 2) * 64 + r] = kv.z;
            KtPs[(c4 + 3) * 64 + r] = kv.w;
            float4 vv = *(const float4*)(Vp + r * 64 + c4);
            *(float4*)&Vs[r * 64 + c4] = vv;
        }
        __syncthreads();

        // S = Q K^T  (scaled); s[i][j]: row ty*4+i, col tx*4+j
        float s[4][4];
#pragma unroll
        for (int i = 0; i < 4; i++)
#pragma unroll
            for (int j = 0; j < 4; j++) s[i][j] = 0.f;

#pragma unroll 8
        for (int k = 0; k < 64; k++) {
            float4 q4 = *(const float4*)&Qt[k * 64 + (ty << 2)];
            float4 k4 = *(const float4*)&KtPs[k * 64 + (tx << 2)];
            float qa[4] = {q4.x, q4.y, q4.z, q4.w};
            float kb[4] = {k4.x, k4.y, k4.z, k4.w};
#pragma unroll
            for (int i = 0; i < 4; i++)
#pragma unroll
                for (int j = 0; j < 4; j++)
                    s[i][j] = fmaf(qa[i], kb[j], s[i][j]);
        }

        // Causal mask (diagonal tile only: k0 == q0 since BM == BN)
        if (k0 == q0) {
#pragma unroll
            for (int i = 0; i < 4; i++)
#pragma unroll
                for (int j = 0; j < 4; j++)
                    if (((tx << 2) + j) > ((ty << 2) + i)) s[i][j] = NEG_INF;
        }

        // Online softmax update
#pragma unroll
        for (int i = 0; i < 4; i++) {
            float tmax = fmaxf(fmaxf(s[i][0], s[i][1]), fmaxf(s[i][2], s[i][3]));
#pragma unroll
            for (int off = 1; off < 16; off <<= 1)
                tmax = fmaxf(tmax, __shfl_xor_sync(0xffffffffu, tmax, off));
            float mnew = fmaxf(mrow[i], tmax);
            float fac = __expf(mrow[i] - mnew);
            float rs = 0.f;
#pragma unroll
            for (int j = 0; j < 4; j++) {
                float p = __expf(s[i][j] - mnew);
                s[i][j] = p;
                rs += p;
            }
#pragma unroll
            for (int off = 1; off < 16; off <<= 1)
                rs += __shfl_xor_sync(0xffffffffu, rs, off);
            lrow[i] = lrow[i] * fac + rs;
            mrow[i] = mnew;
#pragma unroll
            for (int j = 0; j < 4; j++) acc[i][j] *= fac;
        }

        __syncthreads();  // all Kt reads done before Ps overwrites the buffer
#pragma unroll
        for (int i = 0; i < 4; i++)
            *(float4*)&KtPs[((ty << 2) + i) * 64 + (tx << 2)] =
                make_float4(s[i][0], s[i][1], s[i][2], s[i][3]);
        __syncthreads();

        // O += P V ; thread owns rows ty*4+i, d-cols tx*4+j
#pragma unroll 8
        for (int j = 0; j < 64; j++) {
            float4 v4 = *(const float4*)&Vs[j * 64 + (tx << 2)];
#pragma unroll
            for (int i = 0; i < 4; i++) {
                float p = KtPs[((ty << 2) + i) * 64 + j];   // broadcast
                acc[i][0] = fmaf(p, v4.x, acc[i][0]);
                acc[i][1] = fmaf(p, v4.y, acc[i][1]);
                acc[i][2] = fmaf(p, v4.z, acc[i][2]);
                acc[i][3] = fmaf(p, v4.w, acc[i][3]);
            }
        }
    }

    // Epilogue: divide by l, store to (b*T+t, h*64+dd) row-major
#pragma unroll
    for (int i = 0; i < 4; i++) {
        float inv = 1.0f / lrow[i];
        int qr = q0 + (ty << 2) + i;
        float4 o = make_float4(acc[i][0] * inv, acc[i][1] * inv,
                               acc[i][2] * inv, acc[i][3] * inv);
        *(float4*)&Og[((size_t)(b * T_SZ) + qr) * D_MODEL + h * 64 + (tx << 2)] = o;
    }
}

// ---------------------------------------------------------------------------
extern "C" void kernel_launch(void* const* d_in, const int* in_sizes, int n_in,
                              void* d_out, int out_size)
{
    const float* x_q  = (const float*)d_in[0];
    const float* x_kv = (const float*)d_in[1];
    const float* Wq   = (const float*)d_in[2];
    const float* Wk   = (const float*)d_in[3];
    const float* Wv   = (const float*)d_in[4];
    const float* Wo   = (const float*)d_in[5];
    float* out = (float*)d_out;

    float *pq, *pk, *pv, *pattn;
    cudaGetSymbolAddress((void**)&pq,    g_q);
    cudaGetSymbolAddress((void**)&pk,    g_k);
    cudaGetSymbolAddress((void**)&pv,    g_v);
    cudaGetSymbolAddress((void**)&pattn, g_attn);

    dim3 ggrid(D_MODEL / 128, M_ROWS / 128);   // (8, 64)

    gemm_nt_kernel<1><<<ggrid, 256>>>(x_q,  Wq, pq, M_ROWS, D_MODEL, D_MODEL);
    gemm_nt_kernel<1><<<ggrid, 256>>>(x_kv, Wk, pk, M_ROWS, D_MODEL, D_MODEL);
    gemm_nt_kernel<1><<<ggrid, 256>>>(x_kv, Wv, pv, M_ROWS, D_MODEL, D_MODEL);

    attn_kernel<<<dim3(T_SZ / 64, NUM_HEADS, B_SZ), 256>>>(pq, pk, pv, pattn);

    gemm_nt_kernel<0><<<ggrid, 256>>>(pattn, Wo, out, M_ROWS, D_MODEL, D_MODEL);
}

// round 5
// speedup vs baseline: 2.1496x; 2.1496x over previous
#include <cuda_runtime.h>
#include <cstdint>

#define D_MODEL   1024
#define NUM_HEADS 16
#define HEAD_DIM  64
#define B_SZ      4
#define T_SZ      2048
#define M_ROWS    (B_SZ * T_SZ)   // 8192

// Scratch (allocation-free rule: __device__ globals)
__device__ float g_q[(size_t)B_SZ * NUM_HEADS * T_SZ * HEAD_DIM];    // (b,h,t,d)
__device__ float g_k[(size_t)B_SZ * NUM_HEADS * T_SZ * HEAD_DIM];
__device__ float g_v[(size_t)B_SZ * NUM_HEADS * T_SZ * HEAD_DIM];
__device__ float g_attn[(size_t)M_ROWS * D_MODEL];                   // (b*T+t, c)

// ---------------------------------------------------------------------------
// helpers
// ---------------------------------------------------------------------------
__device__ __forceinline__ uint32_t f2tf32(float x) {
    uint32_t r;
    asm("cvt.rna.tf32.f32 %0, %1;" : "=r"(r) : "f"(x));
    return r;
}

// D = A(16x8, row, tf32) * B(8x8, col, tf32) + C   (fp32 accum)
__device__ __forceinline__ void mma8(float4& d, const uint32_t* a,
                                     uint32_t b0, uint32_t b1, const float4& c) {
    asm volatile(
        "mma.sync.aligned.m16n8k8.row.col.f32.tf32.tf32.f32 "
        "{%0,%1,%2,%3}, {%4,%5,%6,%7}, {%8,%9}, {%10,%11,%12,%13};\n"
        : "=f"(d.x), "=f"(d.y), "=f"(d.z), "=f"(d.w)
        : "r"(a[0]), "r"(a[1]), "r"(a[2]), "r"(a[3]),
          "r"(b0), "r"(b1),
          "f"(c.x), "f"(c.y), "f"(c.z), "f"(c.w));
}

// ---------------------------------------------------------------------------
// C[M,N] = A[M,K] @ W[N,K]^T via tf32 tensor cores.
// BM=BN=128, BK=32, 256 threads = 8 warps (2x4 grid of 64x32 warp tiles).
// Smem [k][m] / [k][n], stride 136 words -> conflict-free fragment loads.
// MODE 0: row-major store. MODE 1: scatter to (b,h,t,d).
// ---------------------------------------------------------------------------
template <int MODE>
__global__ __launch_bounds__(256)
void gemm_tf32_kernel(const float* __restrict__ A, const float* __restrict__ W,
                      float* __restrict__ C)
{
    __shared__ uint32_t Ast[32 * 136];
    __shared__ uint32_t Bst[32 * 136];

    const int tid = threadIdx.x;
    const int lane = tid & 31;
    const int w = tid >> 5;
    const int g  = lane >> 2;    // group id 0..7
    const int t4 = lane & 3;     // thread-in-group
    const int wm = (w >> 2) * 64;  // warp m-offset (0 or 64)
    const int wn = (w & 3) * 32;   // warp n-offset (0..96)
    const int m0 = blockIdx.y << 7;
    const int n0 = blockIdx.x << 7;

    const float* Ap = A + (size_t)m0 * D_MODEL;
    const float* Wp = W + (size_t)n0 * D_MODEL;

    float4 acc[4][4];
#pragma unroll
    for (int i = 0; i < 4; i++)
#pragma unroll
        for (int j = 0; j < 4; j++) acc[i][j] = make_float4(0.f, 0.f, 0.f, 0.f);

    for (int kt = 0; kt < D_MODEL; kt += 32) {
        // stage: 1024 float4 per matrix, 4 per thread. r = v&127, kq = v>>7.
#pragma unroll
        for (int i = 0; i < 4; i++) {
            int v  = tid + (i << 8);
            int r  = v & 127;
            int c4 = (v >> 7) << 2;   // 0..28
            float4 av = *(const float4*)(Ap + (size_t)r * D_MODEL + kt + c4);
            Ast[(c4 + 0) * 136 + r] = f2tf32(av.x);
            Ast[(c4 + 1) * 136 + r] = f2tf32(av.y);
            Ast[(c4 + 2) * 136 + r] = f2tf32(av.z);
            Ast[(c4 + 3) * 136 + r] = f2tf32(av.w);
            float4 bv = *(const float4*)(Wp + (size_t)r * D_MODEL + kt + c4);
            Bst[(c4 + 0) * 136 + r] = f2tf32(bv.x);
            Bst[(c4 + 1) * 136 + r] = f2tf32(bv.y);
            Bst[(c4 + 2) * 136 + r] = f2tf32(bv.z);
            Bst[(c4 + 3) * 136 + r] = f2tf32(bv.w);
        }
        __syncthreads();

#pragma unroll
        for (int ks = 0; ks < 4; ks++) {
            const int kk = ks * 8 + t4;
            uint32_t a[4][4], b[4][2];
#pragma unroll
            for (int mt = 0; mt < 4; mt++) {
                int m = wm + mt * 16 + g;
                a[mt][0] = Ast[kk * 136 + m];
                a[mt][1] = Ast[kk * 136 + m + 8];
                a[mt][2] = Ast[(kk + 4) * 136 + m];
                a[mt][3] = Ast[(kk + 4) * 136 + m + 8];
            }
#pragma unroll
            for (int nt = 0; nt < 4; nt++) {
                int n = wn + nt * 8 + g;
                b[nt][0] = Bst[kk * 136 + n];
                b[nt][1] = Bst[(kk + 4) * 136 + n];
            }
#pragma unroll
            for (int mt = 0; mt < 4; mt++)
#pragma unroll
                for (int nt = 0; nt < 4; nt++)
                    mma8(acc[mt][nt], a[mt], b[nt][0], b[nt][1], acc[mt][nt]);
        }
        __syncthreads();
    }

    // epilogue: per (mt,nt) fragment rows (g, g+8), cols (2*t4, 2*t4+1)
#pragma unroll
    for (int mt = 0; mt < 4; mt++) {
        int r1 = m0 + wm + mt * 16 + g;
        int r2 = r1 + 8;
#pragma unroll
        for (int nt = 0; nt < 4; nt++) {
            int c0 = n0 + wn + nt * 8 + 2 * t4;
            float2 lo = make_float2(acc[mt][nt].x, acc[mt][nt].y);
            float2 hi = make_float2(acc[mt][nt].z, acc[mt][nt].w);
            if (MODE == 0) {
                *(float2*)&C[(size_t)r1 * D_MODEL + c0] = lo;
                *(float2*)&C[(size_t)r2 * D_MODEL + c0] = hi;
            } else {
                int hh = c0 >> 6, dd = c0 & 63;
                int b1 = r1 >> 11, t1 = r1 & 2047;
                int b2 = r2 >> 11, t2 = r2 & 2047;
                *(float2*)&g_q[0] = *(float2*)&g_q[0]; // no-op guard against DCE confusion
                *(float2*)&C[(((size_t)b1 * NUM_HEADS + hh) * T_SZ + t1) * HEAD_DIM + dd] = lo;
                *(float2*)&C[(((size_t)b2 * NUM_HEADS + hh) * T_SZ + t2) * HEAD_DIM + dd] = hi;
            }
        }
    }
}

// ---------------------------------------------------------------------------
// Causal flash attention, tf32 tensor cores.
// Block = 64 q-rows x (head, batch); 128 threads = 4 warps, warp owns 16 rows.
// Kp[64][68]: K tile (then aliased as P tile). Vq[64][72]: Q staging, then V.
// All fragment LDS conflict-free by stride choice (68 == 4 mod 32, 72 == 8).
// ---------------------------------------------------------------------------
__global__ __launch_bounds__(128)
void attn_tc_kernel(const float* __restrict__ Qg, const float* __restrict__ Kg,
                    const float* __restrict__ Vg, float* __restrict__ Og)
{
    __shared__ uint32_t Kp[64 * 68];   // K tile / P tile
    __shared__ uint32_t Vq[64 * 72];   // Q staging, then V tile

    const int tid  = threadIdx.x;
    const int lane = tid & 31;
    const int wm   = tid >> 5;          // warp 0..3 -> rows wm*16..
    const int g    = lane >> 2;
    const int t4   = lane & 3;
    const int qt   = blockIdx.x;
    const int q0   = qt << 6;
    const int h    = blockIdx.y;
    const int b    = blockIdx.z;

    const size_t base = ((size_t)(b * NUM_HEADS + h)) * T_SZ * HEAD_DIM;
    const float NEG_INF = __int_as_float(0xff800000);
    const float scale = 0.125f;   // 1/sqrt(64)

    // ---- stage Q (scaled, tf32) into Vq, then grab A-fragments into regs ----
    {
        const float* Qp = Qg + base + (size_t)q0 * HEAD_DIM;
#pragma unroll
        for (int i = 0; i < 8; i++) {
            int v  = tid + (i << 7);
            int r  = v >> 4;
            int c4 = (v & 15) << 2;
            float4 qv = *(const float4*)(Qp + r * 64 + c4);
            uint4 qs;
            qs.x = f2tf32(qv.x * scale);
            qs.y = f2tf32(qv.y * scale);
            qs.z = f2tf32(qv.z * scale);
            qs.w = f2tf32(qv.w * scale);
            *(uint4*)&Vq[r * 72 + c4] = qs;
        }
    }
    __syncthreads();

    uint32_t qa[8][4];
    {
        int r0 = wm * 16 + g;
#pragma unroll
        for (int ks = 0; ks < 8; ks++) {
            int kk = ks * 8 + t4;
            qa[ks][0] = Vq[r0 * 72 + kk];
            qa[ks][1] = Vq[(r0 + 8) * 72 + kk];
            qa[ks][2] = Vq[r0 * 72 + kk + 4];
            qa[ks][3] = Vq[(r0 + 8) * 72 + kk + 4];
        }
    }

    float4 o[8];
#pragma unroll
    for (int dt = 0; dt < 8; dt++) o[dt] = make_float4(0.f, 0.f, 0.f, 0.f);
    float m0r = NEG_INF, m1r = NEG_INF, l0r = 0.f, l1r = 0.f;

    for (int kt = 0; kt <= qt; kt++) {
        __syncthreads();   // Vq (Q frags / prev V) and Kp (prev P) free

        // ---- stage K -> Kp, V -> Vq (tf32) ----
        {
            const float* Kp_g = Kg + base + (size_t)(kt << 6) * HEAD_DIM;
            const float* Vp_g = Vg + base + (size_t)(kt << 6) * HEAD_DIM;
#pragma unroll
            for (int i = 0; i < 8; i++) {
                int v  = tid + (i << 7);
                int r  = v >> 4;
                int c4 = (v & 15) << 2;
                float4 kv = *(const float4*)(Kp_g + r * 64 + c4);
                uint4 ks4;
                ks4.x = f2tf32(kv.x); ks4.y = f2tf32(kv.y);
                ks4.z = f2tf32(kv.z); ks4.w = f2tf32(kv.w);
                *(uint4*)&Kp[r * 68 + c4] = ks4;
                float4 vv = *(const float4*)(Vp_g + r * 64 + c4);
                uint4 vs4;
                vs4.x = f2tf32(vv.x); vs4.y = f2tf32(vv.y);
                vs4.z = f2tf32(vv.z); vs4.w = f2tf32(vv.w);
                *(uint4*)&Vq[r * 72 + c4] = vs4;
            }
        }
        __syncthreads();

        // ---- S = Q K^T : warp computes m16 x n64 ----
        float4 s[8];
#pragma unroll
        for (int nt = 0; nt < 8; nt++) s[nt] = make_float4(0.f, 0.f, 0.f, 0.f);
#pragma unroll
        for (int nt = 0; nt < 8; nt++) {
            int nrow = (nt * 8 + g) * 68;
#pragma unroll
            for (int ks = 0; ks < 8; ks++) {
                int kk = ks * 8 + t4;
                uint32_t b0 = Kp[nrow + kk];
                uint32_t b1 = Kp[nrow + kk + 4];
                mma8(s[nt], qa[ks], b0, b1, s[nt]);
            }
        }

        // ---- causal mask (diagonal tile only) ----
        if (kt == qt) {
            int rlo = wm * 16 + g;
#pragma unroll
            for (int nt = 0; nt < 8; nt++) {
                int c0 = nt * 8 + 2 * t4;
                if (c0     > rlo)     s[nt].x = NEG_INF;
                if (c0 + 1 > rlo)     s[nt].y = NEG_INF;
                if (c0     > rlo + 8) s[nt].z = NEG_INF;
                if (c0 + 1 > rlo + 8) s[nt].w = NEG_INF;
            }
        }

        // ---- online softmax (rows g and g+8; row spread across 4 lanes) ----
        float mx0 = NEG_INF, mx1 = NEG_INF;
#pragma unroll
        for (int nt = 0; nt < 8; nt++) {
            mx0 = fmaxf(mx0, fmaxf(s[nt].x, s[nt].y));
            mx1 = fmaxf(mx1, fmaxf(s[nt].z, s[nt].w));
        }
        mx0 = fmaxf(mx0, __shfl_xor_sync(0xffffffffu, mx0, 1));
        mx0 = fmaxf(mx0, __shfl_xor_sync(0xffffffffu, mx0, 2));
        mx1 = fmaxf(mx1, __shfl_xor_sync(0xffffffffu, mx1, 1));
        mx1 = fmaxf(mx1, __shfl_xor_sync(0xffffffffu, mx1, 2));

        float mn0 = fmaxf(m0r, mx0), mn1 = fmaxf(m1r, mx1);
        float fac0 = __expf(m0r - mn0), fac1 = __expf(m1r - mn1);
        float sum0 = 0.f, sum1 = 0.f;
#pragma unroll
        for (int nt = 0; nt < 8; nt++) {
            s[nt].x = __expf(s[nt].x - mn0);
            s[nt].y = __expf(s[nt].y - mn0);
            s[nt].z = __expf(s[nt].z - mn1);
            s[nt].w = __expf(s[nt].w - mn1);
            sum0 += s[nt].x + s[nt].y;
            sum1 += s[nt].z + s[nt].w;
        }
        sum0 += __shfl_xor_sync(0xffffffffu, sum0, 1);
        sum0 += __shfl_xor_sync(0xffffffffu, sum0, 2);
        sum1 += __shfl_xor_sync(0xffffffffu, sum1, 1);
        sum1 += __shfl_xor_sync(0xffffffffu, sum1, 2);
        l0r = l0r * fac0 + sum0;
        l1r = l1r * fac1 + sum1;
        m0r = mn0; m1r = mn1;
#pragma unroll
        for (int dt = 0; dt < 8; dt++) {
            o[dt].x *= fac0; o[dt].y *= fac0;
            o[dt].z *= fac1; o[dt].w *= fac1;
        }

        __syncthreads();   // all warps finished reading K from Kp

        // ---- store P (tf32) into Kp at this warp's rows ----
        {
            int pr = (wm * 16 + g) * 68;
#pragma unroll
            for (int nt = 0; nt < 8; nt++) {
                int c0 = nt * 8 + 2 * t4;
                uint2 p01, p23;
                p01.x = f2tf32(s[nt].x); p01.y = f2tf32(s[nt].y);
                p23.x = f2tf32(s[nt].z); p23.y = f2tf32(s[nt].w);
                *(uint2*)&Kp[pr + c0]            = p01;
                *(uint2*)&Kp[pr + 8 * 68 + c0]   = p23;
            }
        }
        __syncwarp();      // warp-local: P rows are private to this warp

        // ---- O += P V ----
        {
            int pr = (wm * 16 + g) * 68;
#pragma unroll
            for (int ks = 0; ks < 8; ks++) {
                int kk = ks * 8 + t4;
                uint32_t pa[4];
                pa[0] = Kp[pr + kk];
                pa[1] = Kp[pr + 8 * 68 + kk];
                pa[2] = Kp[pr + kk + 4];
                pa[3] = Kp[pr + 8 * 68 + kk + 4];
#pragma unroll
                for (int dt = 0; dt < 8; dt++) {
                    uint32_t b0 = Vq[kk * 72 + dt * 8 + g];
                    uint32_t b1 = Vq[(kk + 4) * 72 + dt * 8 + g];
                    mma8(o[dt], pa, b0, b1, o[dt]);
                }
            }
        }
    }

    // ---- epilogue: normalize, store to (b*T+t, h*64+d) ----
    float inv0 = 1.0f / l0r, inv1 = 1.0f / l1r;
    int r1 = q0 + wm * 16 + g;
    int r2 = r1 + 8;
#pragma unroll
    for (int dt = 0; dt < 8; dt++) {
        int c0 = h * 64 + dt * 8 + 2 * t4;
        float2 lo = make_float2(o[dt].x * inv0, o[dt].y * inv0);
        float2 hi = make_float2(o[dt].z * inv1, o[dt].w * inv1);
        *(float2*)&Og[((size_t)(b * T_SZ) + r1) * D_MODEL + c0] = lo;
        *(float2*)&Og[((size_t)(b * T_SZ) + r2) * D_MODEL + c0] = hi;
    }
}

// ---------------------------------------------------------------------------
extern "C" void kernel_launch(void* const* d_in, const int* in_sizes, int n_in,
                              void* d_out, int out_size)
{
    const float* x_q  = (const float*)d_in[0];
    const float* x_kv = (const float*)d_in[1];
    const float* Wq   = (const float*)d_in[2];
    const float* Wk   = (const float*)d_in[3];
    const float* Wv   = (const float*)d_in[4];
    const float* Wo   = (const float*)d_in[5];
    float* out = (float*)d_out;

    float *pq, *pk, *pv, *pattn;
    cudaGetSymbolAddress((void**)&pq,    g_q);
    cudaGetSymbolAddress((void**)&pk,    g_k);
    cudaGetSymbolAddress((void**)&pv,    g_v);
    cudaGetSymbolAddress((void**)&pattn, g_attn);

    dim3 ggrid(D_MODEL / 128, M_ROWS / 128);   // (8, 64)

    gemm_tf32_kernel<1><<<ggrid, 256>>>(x_q,  Wq, pq);
    gemm_tf32_kernel<1><<<ggrid, 256>>>(x_kv, Wk, pk);
    gemm_tf32_kernel<1><<<ggrid, 256>>>(x_kv, Wv, pv);

    attn_tc_kernel<<<dim3(T_SZ / 64, NUM_HEADS, B_SZ), 128>>>(pq, pk, pv, pattn);

    gemm_tf32_kernel<0><<<ggrid, 256>>>(pattn, Wo, out);
}

// round 7
// speedup vs baseline: 2.9865x; 1.3894x over previous
#include <cuda_runtime.h>
#include <cstdint>

#define D_MODEL   1024
#define NUM_HEADS 16
#define HEAD_DIM  64
#define B_SZ      4
#define T_SZ      2048
#define M_ROWS    (B_SZ * T_SZ)   // 8192

// Scratch (allocation-free rule: __device__ globals)
__device__ float g_q[(size_t)B_SZ * NUM_HEADS * T_SZ * HEAD_DIM];    // (b,h,t,d)
__device__ float g_k[(size_t)B_SZ * NUM_HEADS * T_SZ * HEAD_DIM];
__device__ float g_v[(size_t)B_SZ * NUM_HEADS * T_SZ * HEAD_DIM];
__device__ float g_attn[(size_t)M_ROWS * D_MODEL];                   // (b*T+t, c)

// ---------------------------------------------------------------------------
// helpers
// ---------------------------------------------------------------------------
__device__ __forceinline__ uint32_t f2tf32(float x) {
    uint32_t r;
    asm("cvt.rna.tf32.f32 %0, %1;" : "=r"(r) : "f"(x));
    return r;
}

// D = A(16x8, row, tf32) * B(8x8, col, tf32) + C   (fp32 accum)
__device__ __forceinline__ void mma8(float4& d, const uint32_t* a,
                                     uint32_t b0, uint32_t b1, const float4& c) {
    asm volatile(
        "mma.sync.aligned.m16n8k8.row.col.f32.tf32.tf32.f32 "
        "{%0,%1,%2,%3}, {%4,%5,%6,%7}, {%8,%9}, {%10,%11,%12,%13};\n"
        : "=f"(d.x), "=f"(d.y), "=f"(d.z), "=f"(d.w)
        : "r"(a[0]), "r"(a[1]), "r"(a[2]), "r"(a[3]),
          "r"(b0), "r"(b1),
          "f"(c.x), "f"(c.y), "f"(c.z), "f"(c.w));
}

__device__ __forceinline__ void cpa16(uint32_t s, const void* g) {
    asm volatile("cp.async.cg.shared.global [%0], [%1], 16;" :: "r"(s), "l"(g));
}
#define CP_COMMIT() asm volatile("cp.async.commit_group;")
#define CP_WAIT(n)  asm volatile("cp.async.wait_group %0;" :: "n"(n))

// ---------------------------------------------------------------------------
// C[M,N] = A[M,K] @ W[N,K]^T via tf32 tensor cores.
// BM=BN=128, BK=16, 128 threads = 4 warps (2x2 of 64x64 warp tiles).
// cp.async double-buffered staging (raw f32), cvt.rna at fragment load.
// Smem [m][k] stride 20 words -> all fragment LDS conflict-free (bank 20g+t4).
// MODE 0: row-major store. MODE 1: scatter to (b,h,t,d).
// ---------------------------------------------------------------------------
template <int MODE>
__global__ __launch_bounds__(128, 2)
void gemm_tf32_kernel(const float* __restrict__ A, const float* __restrict__ W,
                      float* __restrict__ C)
{
    __shared__ float Ast[2][128 * 20];
    __shared__ float Bst[2][128 * 20];

    const int tid  = threadIdx.x;
    const int lane = tid & 31;
    const int w    = tid >> 5;
    const int g    = lane >> 2;
    const int t4   = lane & 3;
    const int wm   = (w >> 1) * 64;
    const int wn   = (w & 1) * 64;
    const int m0   = blockIdx.y << 7;
    const int n0   = blockIdx.x << 7;

    const float* Ap = A + (size_t)m0 * D_MODEL;
    const float* Wp = W + (size_t)n0 * D_MODEL;
    const uint32_t sA0 = (uint32_t)__cvta_generic_to_shared(&Ast[0][0]);
    const uint32_t sB0 = (uint32_t)__cvta_generic_to_shared(&Bst[0][0]);

    float4 acc[4][8];
#pragma unroll
    for (int i = 0; i < 4; i++)
#pragma unroll
        for (int j = 0; j < 8; j++) acc[i][j] = make_float4(0.f, 0.f, 0.f, 0.f);

    auto stage = [&](int kt, int buf) {
        uint32_t sA = sA0 + (uint32_t)buf * (128 * 20 * 4);
        uint32_t sB = sB0 + (uint32_t)buf * (128 * 20 * 4);
#pragma unroll
        for (int i = 0; i < 4; i++) {
            int c  = tid + (i << 7);     // 0..511 chunks
            int r  = c >> 2;             // row 0..127
            int c4 = (c & 3) << 2;       // 0,4,8,12
            cpa16(sA + (uint32_t)(r * 20 + c4) * 4, Ap + (size_t)r * D_MODEL + kt + c4);
            cpa16(sB + (uint32_t)(r * 20 + c4) * 4, Wp + (size_t)r * D_MODEL + kt + c4);
        }
    };

    stage(0, 0); CP_COMMIT();

    for (int kti = 0; kti < 64; kti++) {
        if (kti < 63) { stage((kti + 1) << 4, (kti + 1) & 1); CP_COMMIT(); CP_WAIT(1); }
        else          { CP_WAIT(0); }
        __syncthreads();

        const float* As = Ast[kti & 1];
        const float* Bs = Bst[kti & 1];
#pragma unroll
        for (int ks = 0; ks < 2; ks++) {
            const int kk = ks * 8 + t4;
            uint32_t a[4][4], bb[8][2];
#pragma unroll
            for (int mt = 0; mt < 4; mt++) {
                int m = wm + mt * 16 + g;
                a[mt][0] = f2tf32(As[m * 20 + kk]);
                a[mt][1] = f2tf32(As[(m + 8) * 20 + kk]);
                a[mt][2] = f2tf32(As[m * 20 + kk + 4]);
                a[mt][3] = f2tf32(As[(m + 8) * 20 + kk + 4]);
            }
#pragma unroll
            for (int nt = 0; nt < 8; nt++) {
                int n = wn + nt * 8 + g;
                bb[nt][0] = f2tf32(Bs[n * 20 + kk]);
                bb[nt][1] = f2tf32(Bs[n * 20 + kk + 4]);
            }
#pragma unroll
            for (int mt = 0; mt < 4; mt++)
#pragma unroll
                for (int nt = 0; nt < 8; nt++)
                    mma8(acc[mt][nt], a[mt], bb[nt][0], bb[nt][1], acc[mt][nt]);
        }
        __syncthreads();
    }

    // epilogue
#pragma unroll
    for (int mt = 0; mt < 4; mt++) {
        int r1 = m0 + wm + mt * 16 + g;
        int r2 = r1 + 8;
#pragma unroll
        for (int nt = 0; nt < 8; nt++) {
            int c0 = n0 + wn + nt * 8 + 2 * t4;
            float2 lo = make_float2(acc[mt][nt].x, acc[mt][nt].y);
            float2 hi = make_float2(acc[mt][nt].z, acc[mt][nt].w);
            if (MODE == 0) {
                *(float2*)&C[(size_t)r1 * D_MODEL + c0] = lo;
                *(float2*)&C[(size_t)r2 * D_MODEL + c0] = hi;
            } else {
                int hh = c0 >> 6, dd = c0 & 63;
                int b1 = r1 >> 11, t1 = r1 & 2047;
                int b2 = r2 >> 11, t2 = r2 & 2047;
                *(float2*)&C[(((size_t)b1 * NUM_HEADS + hh) * T_SZ + t1) * HEAD_DIM + dd] = lo;
                *(float2*)&C[(((size_t)b2 * NUM_HEADS + hh) * T_SZ + t2) * HEAD_DIM + dd] = hi;
            }
        }
    }
}

// ---------------------------------------------------------------------------
// Causal flash attention, tf32 tensor cores.
// Block = 128 q-rows x (head, batch); 128 threads = 4 warps; warp owns m32
// (rows wm*16.. and 64+wm*16..). Q fragments live in registers (loaded once).
// K/V double-buffered via cp.async (raw f32; cvt at fragment load).
// P round-trips smem with stride 72 (conflict-free stores & A-frag loads).
// Dynamic smem: K[2]+V[2] (4x 64x68) + P (128x72) = 106496 B -> 2 blocks/SM.
// ---------------------------------------------------------------------------
__global__ __launch_bounds__(128, 2)
void attn_tc_kernel(const float* __restrict__ Qg, const float* __restrict__ Kg,
                    const float* __restrict__ Vg, float* __restrict__ Og)
{
    extern __shared__ float smf[];
    // word offsets
    const int KS0 = 0, KS1 = 4352, VS0 = 8704, VS1 = 13056, PSO = 17408;
    uint32_t* Psm = (uint32_t*)(smf + PSO);

    const int tid  = threadIdx.x;
    const int lane = tid & 31;
    const int wm   = tid >> 5;          // warp 0..3
    const int g    = lane >> 2;
    const int t4   = lane & 3;
    const int qt   = (int)(gridDim.x - 1) - (int)blockIdx.x;  // long blocks first
    const int q0   = qt << 7;
    const int h    = blockIdx.y;
    const int b    = blockIdx.z;

    const size_t base = ((size_t)(b * NUM_HEADS + h)) * T_SZ * HEAD_DIM;
    const uint32_t smb = (uint32_t)__cvta_generic_to_shared(smf);
    const float NEG_INF = __int_as_float(0xff800000);

    // ---- stage Q (raw f32) into KS0 (rows 0..63) / VS0 (rows 64..127) ----
    {
        const float* Qp = Qg + base + (size_t)q0 * HEAD_DIM;
#pragma unroll
        for (int i = 0; i < 16; i++) {
            int c  = tid + (i << 7);
            int r  = c >> 4;             // 0..127
            int c4 = (c & 15) << 2;      // 0..60
            int off = (r < 64) ? (KS0 + r * 68 + c4) : (VS0 + (r - 64) * 68 + c4);
            cpa16(smb + (uint32_t)off * 4, Qp + r * 64 + c4);
        }
    }
    CP_COMMIT(); CP_WAIT(0);
    __syncthreads();

    // ---- Q fragments -> registers (scaled + tf32) ----
    uint32_t qa[2][8][4];
#pragma unroll
    for (int mt = 0; mt < 2; mt++) {
        const float* Qs = smf + (mt ? VS0 : KS0);
        const int row = wm * 16 + g;
#pragma unroll
        for (int ks = 0; ks < 8; ks++) {
            int kk = ks * 8 + t4;
            qa[mt][ks][0] = f2tf32(Qs[row * 68 + kk]       * 0.125f);
            qa[mt][ks][1] = f2tf32(Qs[(row + 8) * 68 + kk] * 0.125f);
            qa[mt][ks][2] = f2tf32(Qs[row * 68 + kk + 4]       * 0.125f);
            qa[mt][ks][3] = f2tf32(Qs[(row + 8) * 68 + kk + 4] * 0.125f);
        }
    }
    __syncthreads();

    auto stageKV = [&](int kt, int buf) {
        const float* Kp = Kg + base + (size_t)(kt << 6) * HEAD_DIM;
        const float* Vp = Vg + base + (size_t)(kt << 6) * HEAD_DIM;
        const int ko = buf ? KS1 : KS0;
        const int vo = buf ? VS1 : VS0;
#pragma unroll
        for (int i = 0; i < 8; i++) {
            int c  = tid + (i << 7);
            int r  = c >> 4;             // 0..63
            int c4 = (c & 15) << 2;
            cpa16(smb + (uint32_t)(ko + r * 68 + c4) * 4, Kp + r * 64 + c4);
            cpa16(smb + (uint32_t)(vo + r * 68 + c4) * 4, Vp + r * 64 + c4);
        }
    };

    stageKV(0, 0); CP_COMMIT();

    float4 o[2][8];
#pragma unroll
    for (int mt = 0; mt < 2; mt++)
#pragma unroll
        for (int dt = 0; dt < 8; dt++) o[mt][dt] = make_float4(0.f, 0.f, 0.f, 0.f);
    float mrow[2][2] = {{NEG_INF, NEG_INF}, {NEG_INF, NEG_INF}};
    float lrow[2][2] = {{0.f, 0.f}, {0.f, 0.f}};

    const int nkt = 2 * qt + 2;
    for (int kt = 0; kt < nkt; kt++) {
        if (kt + 1 < nkt) { stageKV(kt + 1, (kt + 1) & 1); CP_COMMIT(); CP_WAIT(1); }
        else              { CP_WAIT(0); }
        __syncthreads();

        const float* Kt = smf + ((kt & 1) ? KS1 : KS0);
        const float* Vt = smf + ((kt & 1) ? VS1 : VS0);
        const int k0 = kt << 6;
        const bool act0 = (kt <= 2 * qt);   // mt0 fully masked on last tile

#pragma unroll
        for (int mt = 0; mt < 2; mt++) {
            if (mt == 0 && !act0) continue;

            // ---- S = Q K^T  (m16 x n64 per row-half pair) ----
            float4 s[8];
#pragma unroll
            for (int nt = 0; nt < 8; nt++) s[nt] = make_float4(0.f, 0.f, 0.f, 0.f);
#pragma unroll
            for (int ks = 0; ks < 8; ks++) {
                int kk = ks * 8 + t4;
#pragma unroll
                for (int nt = 0; nt < 8; nt++) {
                    uint32_t b0 = f2tf32(Kt[(nt * 8 + g) * 68 + kk]);
                    uint32_t b1 = f2tf32(Kt[(nt * 8 + g) * 68 + kk + 4]);
                    mma8(s[nt], qa[mt][ks], b0, b1, s[nt]);
                }
            }

            // ---- causal mask (only tiles overlapping the diagonal) ----
            if (kt >= 2 * qt) {
                int rowA = q0 + mt * 64 + wm * 16 + g;
#pragma unroll
                for (int nt = 0; nt < 8; nt++) {
                    int c0 = k0 + nt * 8 + 2 * t4;
                    if (c0     > rowA)     s[nt].x = NEG_INF;
                    if (c0 + 1 > rowA)     s[nt].y = NEG_INF;
                    if (c0     > rowA + 8) s[nt].z = NEG_INF;
                    if (c0 + 1 > rowA + 8) s[nt].w = NEG_INF;
                }
            }

            // ---- online softmax (rows g and g+8; spread across 4 lanes) ----
            float mx0 = NEG_INF, mx1 = NEG_INF;
#pragma unroll
            for (int nt = 0; nt < 8; nt++) {
                mx0 = fmaxf(mx0, fmaxf(s[nt].x, s[nt].y));
                mx1 = fmaxf(mx1, fmaxf(s[nt].z, s[nt].w));
            }
            mx0 = fmaxf(mx0, __shfl_xor_sync(0xffffffffu, mx0, 1));
            mx0 = fmaxf(mx0, __shfl_xor_sync(0xffffffffu, mx0, 2));
            mx1 = fmaxf(mx1, __shfl_xor_sync(0xffffffffu, mx1, 1));
            mx1 = fmaxf(mx1, __shfl_xor_sync(0xffffffffu, mx1, 2));

            float mn0 = fmaxf(mrow[mt][0], mx0), mn1 = fmaxf(mrow[mt][1], mx1);
            float fac0 = __expf(mrow[mt][0] - mn0), fac1 = __expf(mrow[mt][1] - mn1);
            float sum0 = 0.f, sum1 = 0.f;
#pragma unroll
            for (int nt = 0; nt < 8; nt++) {
                s[nt].x = __expf(s[nt].x - mn0);
                s[nt].y = __expf(s[nt].y - mn0);
                s[nt].z = __expf(s[nt].z - mn1);
                s[nt].w = __expf(s[nt].w - mn1);
                sum0 += s[nt].x + s[nt].y;
                sum1 += s[nt].z + s[nt].w;
            }
            sum0 += __shfl_xor_sync(0xffffffffu, sum0, 1);
            sum0 += __shfl_xor_sync(0xffffffffu, sum0, 2);
            sum1 += __shfl_xor_sync(0xffffffffu, sum1, 1);
            sum1 += __shfl_xor_sync(0xffffffffu, sum1, 2);
            lrow[mt][0] = lrow[mt][0] * fac0 + sum0;
            lrow[mt][1] = lrow[mt][1] * fac1 + sum1;
            mrow[mt][0] = mn0; mrow[mt][1] = mn1;
#pragma unroll
            for (int dt = 0; dt < 8; dt++) {
                o[mt][dt].x *= fac0; o[mt][dt].y *= fac0;
                o[mt][dt].z *= fac1; o[mt][dt].w *= fac1;
            }

            // ---- store P (tf32) to smem, warp-private rows, stride 72 ----
            {
                int pr = (mt * 64 + wm * 16 + g) * 72;
#pragma unroll
                for (int nt = 0; nt < 8; nt++) {
                    int c0 = nt * 8 + 2 * t4;
                    uint2 lo, hi;
                    lo.x = f2tf32(s[nt].x); lo.y = f2tf32(s[nt].y);
                    hi.x = f2tf32(s[nt].z); hi.y = f2tf32(s[nt].w);
                    *(uint2*)&Psm[pr + c0]          = lo;
                    *(uint2*)&Psm[pr + 8 * 72 + c0] = hi;
                }
            }
        }
        __syncwarp();   // P rows are private to this warp

        // ---- O += P V  (V fragments shared across both m-tiles) ----
#pragma unroll
        for (int ks = 0; ks < 8; ks++) {
            int kk = ks * 8 + t4;
            uint32_t pa[2][4];
#pragma unroll
            for (int mt = 0; mt < 2; mt++) {
                int pr = (mt * 64 + wm * 16 + g) * 72;
                pa[mt][0] = Psm[pr + kk];
                pa[mt][1] = Psm[pr + 8 * 72 + kk];
                pa[mt][2] = Psm[pr + kk + 4];
                pa[mt][3] = Psm[pr + 8 * 72 + kk + 4];
            }
#pragma unroll
            for (int dt = 0; dt < 8; dt++) {
                uint32_t b0 = f2tf32(Vt[kk * 68 + dt * 8 + g]);
                uint32_t b1 = f2tf32(Vt[(kk + 4) * 68 + dt * 8 + g]);
                if (act0) mma8(o[0][dt], pa[0], b0, b1, o[0][dt]);
                mma8(o[1][dt], pa[1], b0, b1, o[1][dt]);
            }
        }
        __syncthreads();   // all reads of this stage's K/V done before overwrite
    }

    // ---- epilogue: normalize, store to (b*T+t, h*64+d) ----
#pragma unroll
    for (int mt = 0; mt < 2; mt++) {
        float inv0 = 1.0f / lrow[mt][0], inv1 = 1.0f / lrow[mt][1];
        int r1 = q0 + mt * 64 + wm * 16 + g;
        int r2 = r1 + 8;
#pragma unroll
        for (int dt = 0; dt < 8; dt++) {
            int c0 = h * 64 + dt * 8 + 2 * t4;
            float2 lo = make_float2(o[mt][dt].x * inv0, o[mt][dt].y * inv0);
            float2 hi = make_float2(o[mt][dt].z * inv1, o[mt][dt].w * inv1);
            *(float2*)&Og[((size_t)(b * T_SZ) + r1) * D_MODEL + c0] = lo;
            *(float2*)&Og[((size_t)(b * T_SZ) + r2) * D_MODEL + c0] = hi;
        }
    }
}

// ---------------------------------------------------------------------------
extern "C" void kernel_launch(void* const* d_in, const int* in_sizes, int n_in,
                              void* d_out, int out_size)
{
    const float* x_q  = (const float*)d_in[0];
    const float* x_kv = (const float*)d_in[1];
    const float* Wq   = (const float*)d_in[2];
    const float* Wk   = (const float*)d_in[3];
    const float* Wv   = (const float*)d_in[4];
    const float* Wo   = (const float*)d_in[5];
    float* out = (float*)d_out;

    float *pq, *pk, *pv, *pattn;
    cudaGetSymbolAddress((void**)&pq,    g_q);
    cudaGetSymbolAddress((void**)&pk,    g_k);
    cudaGetSymbolAddress((void**)&pv,    g_v);
    cudaGetSymbolAddress((void**)&pattn, g_attn);

    const int ATTN_SMEM = (17408 + 128 * 72) * 4;   // 106496 B
    cudaFuncSetAttribute(attn_tc_kernel,
                         cudaFuncAttributeMaxDynamicSharedMemorySize, ATTN_SMEM);

    dim3 ggrid(D_MODEL / 128, M_ROWS / 128);   // (8, 64)

    gemm_tf32_kernel<1><<<ggrid, 128>>>(x_q,  Wq, pq);
    gemm_tf32_kernel<1><<<ggrid, 128>>>(x_kv, Wk, pk);
    gemm_tf32_kernel<1><<<ggrid, 128>>>(x_kv, Wv, pv);

    attn_tc_kernel<<<dim3(T_SZ / 128, NUM_HEADS, B_SZ), 128, ATTN_SMEM>>>(pq, pk, pv, pattn);

    gemm_tf32_kernel<0><<<ggrid, 128>>>(pattn, Wo, out);
}

// round 8
// speedup vs baseline: 3.2935x; 1.1028x over previous
#include <cuda_runtime.h>
#include <cstdint>

#define D_MODEL   1024
#define NUM_HEADS 16
#define HEAD_DIM  64
#define B_SZ      4
#define T_SZ      2048
#define M_ROWS    (B_SZ * T_SZ)   // 8192

// Scratch (allocation-free rule: __device__ globals). All tf32 bit patterns.
__device__ uint32_t g_xq [(size_t)M_ROWS * D_MODEL];
__device__ uint32_t g_xkv[(size_t)M_ROWS * D_MODEL];
__device__ uint32_t g_wq [(size_t)D_MODEL * D_MODEL];
__device__ uint32_t g_wk [(size_t)D_MODEL * D_MODEL];
__device__ uint32_t g_wv [(size_t)D_MODEL * D_MODEL];
__device__ uint32_t g_wo [(size_t)D_MODEL * D_MODEL];
__device__ uint32_t g_q  [(size_t)B_SZ * NUM_HEADS * T_SZ * HEAD_DIM];  // (b,h,t,d), pre-scaled
__device__ uint32_t g_k  [(size_t)B_SZ * NUM_HEADS * T_SZ * HEAD_DIM];
__device__ uint32_t g_v  [(size_t)B_SZ * NUM_HEADS * T_SZ * HEAD_DIM];
__device__ uint32_t g_attn[(size_t)M_ROWS * D_MODEL];                   // (b*T+t, c)

// ---------------------------------------------------------------------------
// helpers
// ---------------------------------------------------------------------------
__device__ __forceinline__ uint32_t f2tf32(float x) {
    uint32_t r;
    asm("cvt.rna.tf32.f32 %0, %1;" : "=r"(r) : "f"(x));
    return r;
}

// D = A(16x8, row, tf32) * B(8x8, col, tf32) + C   (fp32 accum)
__device__ __forceinline__ void mma8(float4& d, const uint32_t* a,
                                     uint32_t b0, uint32_t b1, const float4& c) {
    asm volatile(
        "mma.sync.aligned.m16n8k8.row.col.f32.tf32.tf32.f32 "
        "{%0,%1,%2,%3}, {%4,%5,%6,%7}, {%8,%9}, {%10,%11,%12,%13};\n"
        : "=f"(d.x), "=f"(d.y), "=f"(d.z), "=f"(d.w)
        : "r"(a[0]), "r"(a[1]), "r"(a[2]), "r"(a[3]),
          "r"(b0), "r"(b1),
          "f"(c.x), "f"(c.y), "f"(c.z), "f"(c.w));
}

__device__ __forceinline__ void cpa16(uint32_t s, const void* g) {
    asm volatile("cp.async.cg.shared.global [%0], [%1], 16;" :: "r"(s), "l"(g));
}
#define CP_COMMIT() asm volatile("cp.async.commit_group;")
#define CP_WAIT(n)  asm volatile("cp.async.wait_group %0;" :: "n"(n))

// ---------------------------------------------------------------------------
// fp32 -> tf32 bit-pattern conversion (bandwidth-bound pre-pass)
// ---------------------------------------------------------------------------
__global__ __launch_bounds__(256)
void cvt_tf32_kernel(const float4* __restrict__ src, uint4* __restrict__ dst, int n4)
{
    int i = blockIdx.x * 256 + threadIdx.x;
    if (i < n4) {
        float4 v = src[i];
        uint4 o;
        o.x = f2tf32(v.x); o.y = f2tf32(v.y);
        o.z = f2tf32(v.z); o.w = f2tf32(v.w);
        dst[i] = o;
    }
}

// ---------------------------------------------------------------------------
// GEMM mainloop core: BM=BN=128, BK=16, 256 threads = 8 warps (2x4 of 64x32).
// Operands are pre-converted tf32 bits: LDS only, no cvt in the loop.
// Smem [m][k] stride 20 words -> all fragment LDS conflict-free.
// ---------------------------------------------------------------------------
#define GEMM_MAIN(A_, W_)                                                      \
    __shared__ uint32_t Ast[2][128 * 20];                                      \
    __shared__ uint32_t Bst[2][128 * 20];                                      \
    const int tid  = threadIdx.x;                                              \
    const int lane = tid & 31;                                                 \
    const int w    = tid >> 5;                                                 \
    const int g    = lane >> 2;                                                \
    const int t4   = lane & 3;                                                 \
    const int wm   = (w >> 2) * 64;                                            \
    const int wn   = (w & 3) * 32;                                             \
    const int m0   = blockIdx.y << 7;                                          \
    const int n0   = blockIdx.x << 7;                                          \
    const uint32_t* Ap = (A_) + (size_t)m0 * D_MODEL;                          \
    const uint32_t* Wp = (W_) + (size_t)n0 * D_MODEL;                          \
    const uint32_t sA0 = (uint32_t)__cvta_generic_to_shared(&Ast[0][0]);       \
    const uint32_t sB0 = (uint32_t)__cvta_generic_to_shared(&Bst[0][0]);       \
    float4 acc[4][4];                                                          \
    for (int i = 0; i < 4; i++)                                                \
        for (int j = 0; j < 4; j++) acc[i][j] = make_float4(0.f,0.f,0.f,0.f);  \
    auto stage = [&](int kt, int buf) {                                        \
        uint32_t sA = sA0 + (uint32_t)buf * (128 * 20 * 4);                    \
        uint32_t sB = sB0 + (uint32_t)buf * (128 * 20 * 4);                    \
        _Pragma("unroll")                                                      \
        for (int i = 0; i < 2; i++) {                                          \
            int c  = tid + (i << 8);                                           \
            int r  = c >> 2;                                                   \
            int c4 = (c & 3) << 2;                                             \
            cpa16(sA + (uint32_t)(r * 20 + c4) * 4,                            \
                  Ap + (size_t)r * D_MODEL + kt + c4);                         \
            cpa16(sB + (uint32_t)(r * 20 + c4) * 4,                            \
                  Wp + (size_t)r * D_MODEL + kt + c4);                         \
        }                                                                      \
    };                                                                         \
    stage(0, 0); CP_COMMIT();                                                  \
    for (int kti = 0; kti < 64; kti++) {                                       \
        if (kti < 63) { stage((kti + 1) << 4, (kti + 1) & 1); CP_COMMIT();     \
                        CP_WAIT(1); }                                          \
        else          { CP_WAIT(0); }                                          \
        __syncthreads();                                                       \
        const uint32_t* As = Ast[kti & 1];                                     \
        const uint32_t* Bs = Bst[kti & 1];                                     \
        _Pragma("unroll")                                                      \
        for (int ks = 0; ks < 2; ks++) {                                       \
            const int kk = ks * 8 + t4;                                        \
            uint32_t a[4][4], bb[4][2];                                        \
            _Pragma("unroll")                                                  \
            for (int mt = 0; mt < 4; mt++) {                                   \
                int m = wm + mt * 16 + g;                                      \
                a[mt][0] = As[m * 20 + kk];                                    \
                a[mt][1] = As[(m + 8) * 20 + kk];                              \
                a[mt][2] = As[m * 20 + kk + 4];                                \
                a[mt][3] = As[(m + 8) * 20 + kk + 4];                          \
            }                                                                  \
            _Pragma("unroll")                                                  \
            for (int nt = 0; nt < 4; nt++) {                                   \
                int n = wn + nt * 8 + g;                                       \
                bb[nt][0] = Bs[n * 20 + kk];                                   \
                bb[nt][1] = Bs[n * 20 + kk + 4];                               \
            }                                                                  \
            _Pragma("unroll")                                                  \
            for (int mt = 0; mt < 4; mt++)                                     \
                _Pragma("unroll")                                              \
                for (int nt = 0; nt < 4; nt++)                                 \
                    mma8(acc[mt][nt], a[mt], bb[nt][0], bb[nt][1], acc[mt][nt]);\
        }                                                                      \
        __syncthreads();                                                       \
    }

// ---------------------------------------------------------------------------
// Fused Q/K/V projection: z selects (A, W, C, scale). Epilogue scatters to
// (b,h,t,d) as tf32 bits (Q pre-scaled by 1/sqrt(HEAD_DIM)).
// ---------------------------------------------------------------------------
__global__ __launch_bounds__(256, 2)
void gemm_qkv_kernel()
{
    const uint32_t* Asel; const uint32_t* Wsel; uint32_t* Csel; float scale;
    if (blockIdx.z == 0)      { Asel = g_xq;  Wsel = g_wq; Csel = g_q; scale = 0.125f; }
    else if (blockIdx.z == 1) { Asel = g_xkv; Wsel = g_wk; Csel = g_k; scale = 1.0f; }
    else                      { Asel = g_xkv; Wsel = g_wv; Csel = g_v; scale = 1.0f; }

    GEMM_MAIN(Asel, Wsel)

#pragma unroll
    for (int mt = 0; mt < 4; mt++) {
        int r1 = m0 + wm + mt * 16 + g;
        int r2 = r1 + 8;
#pragma unroll
        for (int nt = 0; nt < 4; nt++) {
            int c0 = n0 + wn + nt * 8 + 2 * t4;
            uint2 lo, hi;
            lo.x = f2tf32(acc[mt][nt].x * scale);
            lo.y = f2tf32(acc[mt][nt].y * scale);
            hi.x = f2tf32(acc[mt][nt].z * scale);
            hi.y = f2tf32(acc[mt][nt].w * scale);
            int hh = c0 >> 6, dd = c0 & 63;
            int b1 = r1 >> 11, t1 = r1 & 2047;
            int b2 = r2 >> 11, t2 = r2 & 2047;
            *(uint2*)&Csel[(((size_t)b1 * NUM_HEADS + hh) * T_SZ + t1) * HEAD_DIM + dd] = lo;
            *(uint2*)&Csel[(((size_t)b2 * NUM_HEADS + hh) * T_SZ + t2) * HEAD_DIM + dd] = hi;
        }
    }
}

// ---------------------------------------------------------------------------
// Output projection: A = g_attn (tf32 bits), W = g_wo, C = fp32 row-major.
// ---------------------------------------------------------------------------
__global__ __launch_bounds__(256, 2)
void gemm_o_kernel(float* __restrict__ C)
{
    GEMM_MAIN(g_attn, g_wo)

#pragma unroll
    for (int mt = 0; mt < 4; mt++) {
        int r1 = m0 + wm + mt * 16 + g;
        int r2 = r1 + 8;
#pragma unroll
        for (int nt = 0; nt < 4; nt++) {
            int c0 = n0 + wn + nt * 8 + 2 * t4;
            *(float2*)&C[(size_t)r1 * D_MODEL + c0] =
                make_float2(acc[mt][nt].x, acc[mt][nt].y);
            *(float2*)&C[(size_t)r2 * D_MODEL + c0] =
                make_float2(acc[mt][nt].z, acc[mt][nt].w);
        }
    }
}

// ---------------------------------------------------------------------------
// Causal flash attention, tf32 tensor cores. Operands already tf32 bits
// (Q pre-scaled) -> zero cvt in S/PV loops; P keeps its 32 cvts per tile.
// Block = 128 q-rows; 128 threads = 4 warps; warp owns m32.
// K/V double-buffered via cp.async. P round-trips smem (stride 72).
// ---------------------------------------------------------------------------
__global__ __launch_bounds__(128, 2)
void attn_tc_kernel(const uint32_t* __restrict__ Qg, const uint32_t* __restrict__ Kg,
                    const uint32_t* __restrict__ Vg, uint32_t* __restrict__ Og)
{
    extern __shared__ uint32_t smu[];
    // word offsets
    const int KS0 = 0, KS1 = 4352, VS0 = 8704, VS1 = 13056, PSO = 17408;
    uint32_t* Psm = smu + PSO;

    const int tid  = threadIdx.x;
    const int lane = tid & 31;
    const int wm   = tid >> 5;          // warp 0..3
    const int g    = lane >> 2;
    const int t4   = lane & 3;
    const int qt   = (int)(gridDim.x - 1) - (int)blockIdx.x;  // long blocks first
    const int q0   = qt << 7;
    const int h    = blockIdx.y;
    const int b    = blockIdx.z;

    const size_t base = ((size_t)(b * NUM_HEADS + h)) * T_SZ * HEAD_DIM;
    const uint32_t smb = (uint32_t)__cvta_generic_to_shared(smu);
    const float NEG_INF = __int_as_float(0xff800000);

    // ---- stage Q (tf32 bits) into KS0 (rows 0..63) / VS0 (rows 64..127) ----
    {
        const uint32_t* Qp = Qg + base + (size_t)q0 * HEAD_DIM;
#pragma unroll
        for (int i = 0; i < 16; i++) {
            int c  = tid + (i << 7);
            int r  = c >> 4;             // 0..127
            int c4 = (c & 15) << 2;      // 0..60
            int off = (r < 64) ? (KS0 + r * 68 + c4) : (VS0 + (r - 64) * 68 + c4);
            cpa16(smb + (uint32_t)off * 4, Qp + r * 64 + c4);
        }
    }
    CP_COMMIT(); CP_WAIT(0);
    __syncthreads();

    // ---- Q fragments -> registers (raw, already scaled tf32) ----
    uint32_t qa[2][8][4];
#pragma unroll
    for (int mt = 0; mt < 2; mt++) {
        const uint32_t* Qs = smu + (mt ? VS0 : KS0);
        const int row = wm * 16 + g;
#pragma unroll
        for (int ks = 0; ks < 8; ks++) {
            int kk = ks * 8 + t4;
            qa[mt][ks][0] = Qs[row * 68 + kk];
            qa[mt][ks][1] = Qs[(row + 8) * 68 + kk];
            qa[mt][ks][2] = Qs[row * 68 + kk + 4];
            qa[mt][ks][3] = Qs[(row + 8) * 68 + kk + 4];
        }
    }
    __syncthreads();

    auto stageKV = [&](int kt, int buf) {
        const uint32_t* Kp = Kg + base + (size_t)(kt << 6) * HEAD_DIM;
        const uint32_t* Vp = Vg + base + (size_t)(kt << 6) * HEAD_DIM;
        const int ko = buf ? KS1 : KS0;
        const int vo = buf ? VS1 : VS0;
#pragma unroll
        for (int i = 0; i < 8; i++) {
            int c  = tid + (i << 7);
            int r  = c >> 4;             // 0..63
            int c4 = (c & 15) << 2;
            cpa16(smb + (uint32_t)(ko + r * 68 + c4) * 4, Kp + r * 64 + c4);
            cpa16(smb + (uint32_t)(vo + r * 68 + c4) * 4, Vp + r * 64 + c4);
        }
    };

    stageKV(0, 0); CP_COMMIT();

    float4 o[2][8];
#pragma unroll
    for (int mt = 0; mt < 2; mt++)
#pragma unroll
        for (int dt = 0; dt < 8; dt++) o[mt][dt] = make_float4(0.f, 0.f, 0.f, 0.f);
    float mrow[2][2] = {{NEG_INF, NEG_INF}, {NEG_INF, NEG_INF}};
    float lrow[2][2] = {{0.f, 0.f}, {0.f, 0.f}};

    const int nkt = 2 * qt + 2;
    for (int kt = 0; kt < nkt; kt++) {
        if (kt + 1 < nkt) { stageKV(kt + 1, (kt + 1) & 1); CP_COMMIT(); CP_WAIT(1); }
        else              { CP_WAIT(0); }
        __syncthreads();

        const uint32_t* Kt = smu + ((kt & 1) ? KS1 : KS0);
        const uint32_t* Vt = smu + ((kt & 1) ? VS1 : VS0);
        const int k0 = kt << 6;
        const bool act0 = (kt <= 2 * qt);   // mt0 fully masked on last tile

#pragma unroll
        for (int mt = 0; mt < 2; mt++) {
            if (mt == 0 && !act0) continue;

            // ---- S = Q K^T  (m16 x n64 per row-half pair) ----
            float4 s[8];
#pragma unroll
            for (int nt = 0; nt < 8; nt++) s[nt] = make_float4(0.f, 0.f, 0.f, 0.f);
#pragma unroll
            for (int ks = 0; ks < 8; ks++) {
                int kk = ks * 8 + t4;
#pragma unroll
                for (int nt = 0; nt < 8; nt++) {
                    uint32_t b0 = Kt[(nt * 8 + g) * 68 + kk];
                    uint32_t b1 = Kt[(nt * 8 + g) * 68 + kk + 4];
                    mma8(s[nt], qa[mt][ks], b0, b1, s[nt]);
                }
            }

            // ---- causal mask (only tiles overlapping the diagonal) ----
            if (kt >= 2 * qt) {
                int rowA = q0 + mt * 64 + wm * 16 + g;
#pragma unroll
                for (int nt = 0; nt < 8; nt++) {
                    int c0 = k0 + nt * 8 + 2 * t4;
                    if (c0     > rowA)     s[nt].x = NEG_INF;
                    if (c0 + 1 > rowA)     s[nt].y = NEG_INF;
                    if (c0     > rowA + 8) s[nt].z = NEG_INF;
                    if (c0 + 1 > rowA + 8) s[nt].w = NEG_INF;
                }
            }

            // ---- online softmax (rows g and g+8; spread across 4 lanes) ----
            float mx0 = NEG_INF, mx1 = NEG_INF;
#pragma unroll
            for (int nt = 0; nt < 8; nt++) {
                mx0 = fmaxf(mx0, fmaxf(s[nt].x, s[nt].y));
                mx1 = fmaxf(mx1, fmaxf(s[nt].z, s[nt].w));
            }
            mx0 = fmaxf(mx0, __shfl_xor_sync(0xffffffffu, mx0, 1));
            mx0 = fmaxf(mx0, __shfl_xor_sync(0xffffffffu, mx0, 2));
            mx1 = fmaxf(mx1, __shfl_xor_sync(0xffffffffu, mx1, 1));
            mx1 = fmaxf(mx1, __shfl_xor_sync(0xffffffffu, mx1, 2));

            float mn0 = fmaxf(mrow[mt][0], mx0), mn1 = fmaxf(mrow[mt][1], mx1);
            float fac0 = __expf(mrow[mt][0] - mn0), fac1 = __expf(mrow[mt][1] - mn1);
            float sum0 = 0.f, sum1 = 0.f;
#pragma unroll
            for (int nt = 0; nt < 8; nt++) {
                s[nt].x = __expf(s[nt].x - mn0);
                s[nt].y = __expf(s[nt].y - mn0);
                s[nt].z = __expf(s[nt].z - mn1);
                s[nt].w = __expf(s[nt].w - mn1);
                sum0 += s[nt].x + s[nt].y;
                sum1 += s[nt].z + s[nt].w;
            }
            sum0 += __shfl_xor_sync(0xffffffffu, sum0, 1);
            sum0 += __shfl_xor_sync(0xffffffffu, sum0, 2);
            sum1 += __shfl_xor_sync(0xffffffffu, sum1, 1);
            sum1 += __shfl_xor_sync(0xffffffffu, sum1, 2);
            lrow[mt][0] = lrow[mt][0] * fac0 + sum0;
            lrow[mt][1] = lrow[mt][1] * fac1 + sum1;
            mrow[mt][0] = mn0; mrow[mt][1] = mn1;
#pragma unroll
            for (int dt = 0; dt < 8; dt++) {
                o[mt][dt].x *= fac0; o[mt][dt].y *= fac0;
                o[mt][dt].z *= fac1; o[mt][dt].w *= fac1;
            }

            // ---- store P (tf32) to smem, warp-private rows, stride 72 ----
            {
                int pr = (mt * 64 + wm * 16 + g) * 72;
#pragma unroll
                for (int nt = 0; nt < 8; nt++) {
                    int c0 = nt * 8 + 2 * t4;
                    uint2 lo, hi;
                    lo.x = f2tf32(s[nt].x); lo.y = f2tf32(s[nt].y);
                    hi.x = f2tf32(s[nt].z); hi.y = f2tf32(s[nt].w);
                    *(uint2*)&Psm[pr + c0]          = lo;
                    *(uint2*)&Psm[pr + 8 * 72 + c0] = hi;
                }
            }
        }
        __syncwarp();   // P rows are private to this warp

        // ---- O += P V  (V fragments shared across both m-tiles) ----
#pragma unroll
        for (int ks = 0; ks < 8; ks++) {
            int kk = ks * 8 + t4;
            uint32_t pa[2][4];
#pragma unroll
            for (int mt = 0; mt < 2; mt++) {
                int pr = (mt * 64 + wm * 16 + g) * 72;
                pa[mt][0] = Psm[pr + kk];
                pa[mt][1] = Psm[pr + 8 * 72 + kk];
                pa[mt][2] = Psm[pr + kk + 4];
                pa[mt][3] = Psm[pr + 8 * 72 + kk + 4];
            }
#pragma unroll
            for (int dt = 0; dt < 8; dt++) {
                uint32_t b0 = Vt[kk * 68 + dt * 8 + g];
                uint32_t b1 = Vt[(kk + 4) * 68 + dt * 8 + g];
                if (act0) mma8(o[0][dt], pa[0], b0, b1, o[0][dt]);
                mma8(o[1][dt], pa[1], b0, b1, o[1][dt]);
            }
        }
        __syncthreads();   // all reads of this stage's K/V done before overwrite
    }

    // ---- epilogue: normalize, store tf32 bits to (b*T+t, h*64+d) ----
#pragma unroll
    for (int mt = 0; mt < 2; mt++) {
        float inv0 = 1.0f / lrow[mt][0], inv1 = 1.0f / lrow[mt][1];
        int r1 = q0 + mt * 64 + wm * 16 + g;
        int r2 = r1 + 8;
#pragma unroll
        for (int dt = 0; dt < 8; dt++) {
            int c0 = h * 64 + dt * 8 + 2 * t4;
            uint2 lo, hi;
            lo.x = f2tf32(o[mt][dt].x * inv0); lo.y = f2tf32(o[mt][dt].y * inv0);
            hi.x = f2tf32(o[mt][dt].z * inv1); hi.y = f2tf32(o[mt][dt].w * inv1);
            *(uint2*)&Og[((size_t)(b * T_SZ) + r1) * D_MODEL + c0] = lo;
            *(uint2*)&Og[((size_t)(b * T_SZ) + r2) * D_MODEL + c0] = hi;
        }
    }
}

// ---------------------------------------------------------------------------
extern "C" void kernel_launch(void* const* d_in, const int* in_sizes, int n_in,
                              void* d_out, int out_size)
{
    const float* x_q  = (const float*)d_in[0];
    const float* x_kv = (const float*)d_in[1];
    const float* Wq   = (const float*)d_in[2];
    const float* Wk   = (const float*)d_in[3];
    const float* Wv   = (const float*)d_in[4];
    const float* Wo   = (const float*)d_in[5];
    float* out = (float*)d_out;

    uint32_t *pxq, *pxkv, *pwq, *pwk, *pwv, *pwo, *pq, *pk, *pv, *pattn;
    cudaGetSymbolAddress((void**)&pxq,  g_xq);
    cudaGetSymbolAddress((void**)&pxkv, g_xkv);
    cudaGetSymbolAddress((void**)&pwq,  g_wq);
    cudaGetSymbolAddress((void**)&pwk,  g_wk);
    cudaGetSymbolAddress((void**)&pwv,  g_wv);
    cudaGetSymbolAddress((void**)&pwo,  g_wo);
    cudaGetSymbolAddress((void**)&pq,   g_q);
    cudaGetSymbolAddress((void**)&pk,   g_k);
    cudaGetSymbolAddress((void**)&pv,   g_v);
    cudaGetSymbolAddress((void**)&pattn, g_attn);

    const int ATTN_SMEM = (17408 + 128 * 72) * 4;   // 106496 B
    cudaFuncSetAttribute(attn_tc_kernel,
                         cudaFuncAttributeMaxDynamicSharedMemorySize, ATTN_SMEM);

    // ---- pre-convert inputs/weights to tf32 bits ----
    const int NX4 = M_ROWS * D_MODEL / 4;     // 2M float4
    const int NW4 = D_MODEL * D_MODEL / 4;    // 256K float4
    cvt_tf32_kernel<<<(NX4 + 255) / 256, 256>>>((const float4*)x_q,  (uint4*)pxq,  NX4);
    cvt_tf32_kernel<<<(NX4 + 255) / 256, 256>>>((const float4*)x_kv, (uint4*)pxkv, NX4);
    cvt_tf32_kernel<<<(NW4 + 255) / 256, 256>>>((const float4*)Wq, (uint4*)pwq, NW4);
    cvt_tf32_kernel<<<(NW4 + 255) / 256, 256>>>((const float4*)Wk, (uint4*)pwk, NW4);
    cvt_tf32_kernel<<<(NW4 + 255) / 256, 256>>>((const float4*)Wv, (uint4*)pwv, NW4);
    cvt_tf32_kernel<<<(NW4 + 255) / 256, 256>>>((const float4*)Wo, (uint4*)pwo, NW4);

    // ---- fused Q/K/V projections ----
    gemm_qkv_kernel<<<dim3(D_MODEL / 128, M_ROWS / 128, 3), 256>>>();

    // ---- attention ----
    attn_tc_kernel<<<dim3(T_SZ / 128, NUM_HEADS, B_SZ), 128, ATTN_SMEM>>>(pq, pk, pv, pattn);

    // ---- output projection ----
    gemm_o_kernel<<<dim3(D_MODEL / 128, M_ROWS / 128), 256>>>(out);
}

// round 10
// speedup vs baseline: 4.0033x; 1.2155x over previous
#include <cuda_runtime.h>
#include <cstdint>

#define D_MODEL   1024
#define NUM_HEADS 16
#define HEAD_DIM  64
#define B_SZ      4
#define T_SZ      2048
#define M_ROWS    (B_SZ * T_SZ)   // 8192

// Scratch (allocation-free rule: __device__ globals). All tf32 bit patterns.
// Arrays feeding a GEMM contraction are stored k-PAIR-PERMUTED within each
// 8-group: pos(k) = (k&~7) | ((k&3)<<1) | ((k>>2)&1).  Both operands of every
// mma use the same permutation, so results are bit-identical to natural order.
__device__ uint32_t g_xq [(size_t)M_ROWS * D_MODEL];     // permuted k
__device__ uint32_t g_xkv[(size_t)M_ROWS * D_MODEL];     // permuted k
__device__ uint32_t g_wq [(size_t)D_MODEL * D_MODEL];    // permuted k
__device__ uint32_t g_wk [(size_t)D_MODEL * D_MODEL];    // permuted k
__device__ uint32_t g_wv [(size_t)D_MODEL * D_MODEL];    // permuted k
__device__ uint32_t g_wo [(size_t)D_MODEL * D_MODEL];    // permuted k
__device__ uint32_t g_q  [(size_t)B_SZ * NUM_HEADS * T_SZ * HEAD_DIM];  // natural d, pre-scaled
__device__ uint32_t g_k  [(size_t)B_SZ * NUM_HEADS * T_SZ * HEAD_DIM];  // PERMUTED d
__device__ uint32_t g_v  [(size_t)B_SZ * NUM_HEADS * T_SZ * HEAD_DIM];  // natural d
__device__ uint32_t g_attn[(size_t)M_ROWS * D_MODEL];                   // permuted c

// ---------------------------------------------------------------------------
// helpers
// ---------------------------------------------------------------------------
__device__ __forceinline__ uint32_t f2tf32(float x) {
    uint32_t r;
    asm("cvt.rna.tf32.f32 %0, %1;" : "=r"(r) : "f"(x));
    return r;
}

__device__ __forceinline__ int kperm(int c) {   // position of logical index c
    return (c & ~7) | ((c & 3) << 1) | ((c >> 2) & 1);
}

// D = A(16x8, row, tf32) * B(8x8, col, tf32) + C   (fp32 accum)
__device__ __forceinline__ void mma8(float4& d, const uint32_t* a,
                                     uint32_t b0, uint32_t b1, const float4& c) {
    asm volatile(
        "mma.sync.aligned.m16n8k8.row.col.f32.tf32.tf32.f32 "
        "{%0,%1,%2,%3}, {%4,%5,%6,%7}, {%8,%9}, {%10,%11,%12,%13};\n"
        : "=f"(d.x), "=f"(d.y), "=f"(d.z), "=f"(d.w)
        : "r"(a[0]), "r"(a[1]), "r"(a[2]), "r"(a[3]),
          "r"(b0), "r"(b1),
          "f"(c.x), "f"(c.y), "f"(c.z), "f"(c.w));
}

__device__ __forceinline__ void cpa16(uint32_t s, const void* g) {
    asm volatile("cp.async.cg.shared.global [%0], [%1], 16;" :: "r"(s), "l"(g));
}
#define CP_COMMIT() asm volatile("cp.async.commit_group;")
#define CP_WAIT(n)  asm volatile("cp.async.wait_group %0;" :: "n"(n))

// ---------------------------------------------------------------------------
// fp32 -> tf32 bits + k-pair permutation. Thread handles 8 consecutive words.
// out[8i..] = {k0,k4,k1,k5,k2,k6,k3,k7}
// ---------------------------------------------------------------------------
__global__ __launch_bounds__(256)
void cvtp_kernel(const float* __restrict__ src, uint32_t* __restrict__ dst, int n8)
{
    int i = blockIdx.x * 256 + threadIdx.x;
    if (i < n8) {
        const float* s = src + (size_t)i * 8;
        float4 v0 = *(const float4*)s;
        float4 v1 = *(const float4*)(s + 4);
        uint4 o0, o1;
        o0.x = f2tf32(v0.x); o0.y = f2tf32(v1.x);
        o0.z = f2tf32(v0.y); o0.w = f2tf32(v1.y);
        o1.x = f2tf32(v0.z); o1.y = f2tf32(v1.z);
        o1.z = f2tf32(v0.w); o1.w = f2tf32(v1.w);
        *(uint4*)(dst + (size_t)i * 8)     = o0;
        *(uint4*)(dst + (size_t)i * 8 + 4) = o1;
    }
}

// ---------------------------------------------------------------------------
// GEMM mainloop: BM=BN=128, BK=32, 256 threads = 8 warps (2x4 of 64x32).
// Operands pre-permuted tf32 bits: each mma fragment is ONE LDS.64 (B) or
// TWO LDS.64 (A). Smem row stride 40 words (8g+2t4 bank pattern, conflict-free).
// Double-buffered cp.async.
// ---------------------------------------------------------------------------
#define GS 40
#define GEMM_MAIN(A_, W_)                                                      \
    extern __shared__ uint32_t smu[];                                          \
    const int tid  = threadIdx.x;                                              \
    const int lane = tid & 31;                                                 \
    const int w    = tid >> 5;                                                 \
    const int g    = lane >> 2;                                                \
    const int t4   = lane & 3;                                                 \
    const int wm   = (w >> 2) * 64;                                            \
    const int wn   = (w & 3) * 32;                                             \
    const int m0   = blockIdx.y << 7;                                          \
    const int n0   = blockIdx.x << 7;                                          \
    const uint32_t* Ap = (A_) + (size_t)m0 * D_MODEL;                          \
    const uint32_t* Wp = (W_) + (size_t)n0 * D_MODEL;                          \
    const uint32_t smb = (uint32_t)__cvta_generic_to_shared(smu);              \
    /* word offsets: A0=0 B0=5120 A1=10240 B1=15360 */                         \
    float4 acc[4][4];                                                          \
    for (int i = 0; i < 4; i++)                                                \
        for (int j = 0; j < 4; j++) acc[i][j] = make_float4(0.f,0.f,0.f,0.f);  \
    auto stage = [&](int kt, int buf) {                                        \
        uint32_t sA = smb + (uint32_t)(buf * 10240) * 4;                       \
        uint32_t sB = sA + 5120u * 4;                                          \
        _Pragma("unroll")                                                      \
        for (int i = 0; i < 4; i++) {                                          \
            int c  = tid + (i << 8);          /* 0..1023 */                    \
            int r  = c >> 3;                                                   \
            int c8 = (c & 7) << 2;                                             \
            cpa16(sA + (uint32_t)(r * GS + c8) * 4,                            \
                  Ap + (size_t)r * D_MODEL + kt + c8);                         \
            cpa16(sB + (uint32_t)(r * GS + c8) * 4,                            \
                  Wp + (size_t)r * D_MODEL + kt + c8);                         \
        }                                                                      \
    };                                                                         \
    stage(0, 0);  CP_COMMIT();                                                 \
    stage(32, 1); CP_COMMIT();                                                 \
    for (int kti = 0; kti < 32; kti++) {                                       \
        if (kti < 31) { CP_WAIT(1); } else { CP_WAIT(0); }                     \
        __syncthreads();                                                       \
        const uint32_t* As = smu + (kti & 1) * 10240;                          \
        const uint32_t* Bs = As + 5120;                                        \
        _Pragma("unroll")                                                      \
        for (int ks = 0; ks < 4; ks++) {                                       \
            const int kk2 = ks * 8 + t4 * 2;                                   \
            uint32_t a[4][4], bb[4][2];                                        \
            _Pragma("unroll")                                                  \
            for (int mt = 0; mt < 4; mt++) {                                   \
                int m = wm + mt * 16 + g;                                      \
                uint2 u = *(const uint2*)&As[m * GS + kk2];                    \
                uint2 v = *(const uint2*)&As[(m + 8) * GS + kk2];              \
                a[mt][0] = u.x; a[mt][1] = v.x;                                \
                a[mt][2] = u.y; a[mt][3] = v.y;                                \
            }                                                                  \
            _Pragma("unroll")                                                  \
            for (int nt = 0; nt < 4; nt++) {                                   \
                int n = wn + nt * 8 + g;                                       \
                uint2 p = *(const uint2*)&Bs[n * GS + kk2];                    \
                bb[nt][0] = p.x; bb[nt][1] = p.y;                              \
            }                                                                  \
            _Pragma("unroll")                                                  \
            for (int mt = 0; mt < 4; mt++)                                     \
                _Pragma("unroll")                                              \
                for (int nt = 0; nt < 4; nt++)                                 \
                    mma8(acc[mt][nt], a[mt], bb[nt][0], bb[nt][1], acc[mt][nt]);\
        }                                                                      \
        __syncthreads();                                                       \
        if (kti + 2 < 32) { stage((kti + 2) << 5, kti & 1); CP_COMMIT(); }     \
    }

// ---------------------------------------------------------------------------
// Fused Q/K/V projection. Epilogue scatters to (b,h,t,d) tf32 bits.
// Q: pre-scaled, natural d. K: d-PERMUTED (for attn LDS.64). V: natural d.
// ---------------------------------------------------------------------------
__global__ __launch_bounds__(256, 2)
void gemm_qkv_kernel()
{
    const uint32_t* Asel; const uint32_t* Wsel; uint32_t* Csel; float scale = 1.0f;
    if (blockIdx.z == 0)      { Asel = g_xq;  Wsel = g_wq; Csel = g_q; scale = 0.125f; }
    else if (blockIdx.z == 1) { Asel = g_xkv; Wsel = g_wk; Csel = g_k; }
    else                      { Asel = g_xkv; Wsel = g_wv; Csel = g_v; }
    const bool permK = (blockIdx.z == 1);

    GEMM_MAIN(Asel, Wsel)

#pragma unroll
    for (int mt = 0; mt < 4; mt++) {
        int r1 = m0 + wm + mt * 16 + g;
        int r2 = r1 + 8;
        int b1 = r1 >> 11, t1 = r1 & 2047;
        int b2 = r2 >> 11, t2 = r2 & 2047;
#pragma unroll
        for (int nt = 0; nt < 4; nt++) {
            int c0 = n0 + wn + nt * 8 + 2 * t4;
            int hh = c0 >> 6, d0 = c0 & 63;
            uint32_t q00 = f2tf32(acc[mt][nt].x * scale);
            uint32_t q01 = f2tf32(acc[mt][nt].y * scale);
            uint32_t q10 = f2tf32(acc[mt][nt].z * scale);
            uint32_t q11 = f2tf32(acc[mt][nt].w * scale);
            size_t base1 = (((size_t)b1 * NUM_HEADS + hh) * T_SZ + t1) * HEAD_DIM;
            size_t base2 = (((size_t)b2 * NUM_HEADS + hh) * T_SZ + t2) * HEAD_DIM;
            if (permK) {
                int p0 = kperm(d0), p1 = kperm(d0 + 1);
                Csel[base1 + p0] = q00;  Csel[base1 + p1] = q01;
                Csel[base2 + p0] = q10;  Csel[base2 + p1] = q11;
            } else {
                *(uint2*)&Csel[base1 + d0] = make_uint2(q00, q01);
                *(uint2*)&Csel[base2 + d0] = make_uint2(q10, q11);
            }
        }
    }
}

// ---------------------------------------------------------------------------
// Output projection: A = g_attn (permuted c), W = g_wo (permuted k),
// C = fp32 row-major (natural N).
// ---------------------------------------------------------------------------
__global__ __launch_bounds__(256, 2)
void gemm_o_kernel(float* __restrict__ C)
{
    GEMM_MAIN(g_attn, g_wo)

#pragma unroll
    for (int mt = 0; mt < 4; mt++) {
        int r1 = m0 + wm + mt * 16 + g;
        int r2 = r1 + 8;
#pragma unroll
        for (int nt = 0; nt < 4; nt++) {
            int c0 = n0 + wn + nt * 8 + 2 * t4;
            *(float2*)&C[(size_t)r1 * D_MODEL + c0] =
                make_float2(acc[mt][nt].x, acc[mt][nt].y);
            *(float2*)&C[(size_t)r2 * D_MODEL + c0] =
                make_float2(acc[mt][nt].z, acc[mt][nt].w);
        }
    }
}

// ---------------------------------------------------------------------------
// Causal flash attention, tf32 mma.sync.
// K is d-permuted in gmem -> S-loop B fragment = ONE LDS.64 (stride 72,
// conflict-free). V natural, stride 72 (fixes the old 2-way conflict at 68).
// Smem (words): K0@0 K1@4608 V0@9216 V1@13824 P@18432(128x72); 110592 B.
// ---------------------------------------------------------------------------
__global__ __launch_bounds__(128, 2)
void attn_tc_kernel(const uint32_t* __restrict__ Qg, const uint32_t* __restrict__ Kg,
                    const uint32_t* __restrict__ Vg, uint32_t* __restrict__ Og)
{
    extern __shared__ uint32_t smu[];
    const int KS0 = 0, KS1 = 4608, VS0 = 9216, VS1 = 13824, PSO = 18432;
    uint32_t* Psm = smu + PSO;

    const int tid  = threadIdx.x;
    const int lane = tid & 31;
    const int wm   = tid >> 5;
    const int g    = lane >> 2;
    const int t4   = lane & 3;
    const int qt   = (int)(gridDim.x - 1) - (int)blockIdx.x;  // long blocks first
    const int q0   = qt << 7;
    const int h    = blockIdx.y;
    const int b    = blockIdx.z;

    const size_t base = ((size_t)(b * NUM_HEADS + h)) * T_SZ * HEAD_DIM;
    const uint32_t smb = (uint32_t)__cvta_generic_to_shared(smu);
    const float NEG_INF = __int_as_float(0xff800000);

    // ---- stage Q (natural, pre-scaled) into KS0 rows 0-63 / VS0 rows 64-127 ----
    {
        const uint32_t* Qp = Qg + base + (size_t)q0 * HEAD_DIM;
#pragma unroll
        for (int i = 0; i < 16; i++) {
            int c  = tid + (i << 7);
            int r  = c >> 4;
            int c4 = (c & 15) << 2;
            int off = (r < 64) ? (KS0 + r * 72 + c4) : (VS0 + (r - 64) * 72 + c4);
            cpa16(smb + (uint32_t)off * 4, Qp + r * 64 + c4);
        }
    }
    CP_COMMIT(); CP_WAIT(0);
    __syncthreads();

    // ---- Q fragments -> registers (logical k order via explicit indexing) ----
    uint32_t qa[2][8][4];
#pragma unroll
    for (int mt = 0; mt < 2; mt++) {
        const uint32_t* Qs = smu + (mt ? VS0 : KS0);
        const int row = wm * 16 + g;
#pragma unroll
        for (int ks = 0; ks < 8; ks++) {
            int kk = ks * 8 + t4;
            qa[mt][ks][0] = Qs[row * 72 + kk];
            qa[mt][ks][1] = Qs[(row + 8) * 72 + kk];
            qa[mt][ks][2] = Qs[row * 72 + kk + 4];
            qa[mt][ks][3] = Qs[(row + 8) * 72 + kk + 4];
        }
    }
    __syncthreads();

    auto stageKV = [&](int kt, int buf) {
        const uint32_t* Kp = Kg + base + (size_t)(kt << 6) * HEAD_DIM;
        const uint32_t* Vp = Vg + base + (size_t)(kt << 6) * HEAD_DIM;
        const int ko = buf ? KS1 : KS0;
        const int vo = buf ? VS1 : VS0;
#pragma unroll
        for (int i = 0; i < 8; i++) {
            int c  = tid + (i << 7);
            int r  = c >> 4;
            int c4 = (c & 15) << 2;
            cpa16(smb + (uint32_t)(ko + r * 72 + c4) * 4, Kp + r * 64 + c4);
            cpa16(smb + (uint32_t)(vo + r * 72 + c4) * 4, Vp + r * 64 + c4);
        }
    };

    stageKV(0, 0); CP_COMMIT();

    float4 o[2][8];
#pragma unroll
    for (int mt = 0; mt < 2; mt++)
#pragma unroll
        for (int dt = 0; dt < 8; dt++) o[mt][dt] = make_float4(0.f, 0.f, 0.f, 0.f);
    float mrow[2][2] = {{NEG_INF, NEG_INF}, {NEG_INF, NEG_INF}};
    float lrow[2][2] = {{0.f, 0.f}, {0.f, 0.f}};

    const int nkt = 2 * qt + 2;
    for (int kt = 0; kt < nkt; kt++) {
        if (kt + 1 < nkt) { stageKV(kt + 1, (kt + 1) & 1); CP_COMMIT(); CP_WAIT(1); }
        else              { CP_WAIT(0); }
        __syncthreads();

        const uint32_t* Kt = smu + ((kt & 1) ? KS1 : KS0);
        const uint32_t* Vt = smu + ((kt & 1) ? VS1 : VS0);
        const int k0 = kt << 6;
        const bool act0 = (kt <= 2 * qt);

#pragma unroll
        for (int mt = 0; mt < 2; mt++) {
            if (mt == 0 && !act0) continue;

            // ---- S = Q K^T : K is d-permuted -> pair fragment = 1 LDS.64 ----
            float4 s[8];
#pragma unroll
            for (int nt = 0; nt < 8; nt++) s[nt] = make_float4(0.f, 0.f, 0.f, 0.f);
#pragma unroll
            for (int ks = 0; ks < 8; ks++) {
                const int kk2 = ks * 8 + t4 * 2;
#pragma unroll
                for (int nt = 0; nt < 8; nt++) {
                    uint2 bp = *(const uint2*)&Kt[(nt * 8 + g) * 72 + kk2];
                    mma8(s[nt], qa[mt][ks], bp.x, bp.y, s[nt]);
                }
            }

            // ---- causal mask ----
            if (kt >= 2 * qt) {
                int rowA = q0 + mt * 64 + wm * 16 + g;
#pragma unroll
                for (int nt = 0; nt < 8; nt++) {
                    int c0 = k0 + nt * 8 + 2 * t4;
                    if (c0     > rowA)     s[nt].x = NEG_INF;
                    if (c0 + 1 > rowA)     s[nt].y = NEG_INF;
                    if (c0     > rowA + 8) s[nt].z = NEG_INF;
                    if (c0 + 1 > rowA + 8) s[nt].w = NEG_INF;
                }
            }

            // ---- online softmax ----
            float mx0 = NEG_INF, mx1 = NEG_INF;
#pragma unroll
            for (int nt = 0; nt < 8; nt++) {
                mx0 = fmaxf(mx0, fmaxf(s[nt].x, s[nt].y));
                mx1 = fmaxf(mx1, fmaxf(s[nt].z, s[nt].w));
            }
            mx0 = fmaxf(mx0, __shfl_xor_sync(0xffffffffu, mx0, 1));
            mx0 = fmaxf(mx0, __shfl_xor_sync(0xffffffffu, mx0, 2));
            mx1 = fmaxf(mx1, __shfl_xor_sync(0xffffffffu, mx1, 1));
            mx1 = fmaxf(mx1, __shfl_xor_sync(0xffffffffu, mx1, 2));

            float mn0 = fmaxf(mrow[mt][0], mx0), mn1 = fmaxf(mrow[mt][1], mx1);
            float fac0 = __expf(mrow[mt][0] - mn0), fac1 = __expf(mrow[mt][1] - mn1);
            float sum0 = 0.f, sum1 = 0.f;
#pragma unroll
            for (int nt = 0; nt < 8; nt++) {
                s[nt].x = __expf(s[nt].x - mn0);
                s[nt].y = __expf(s[nt].y - mn0);
                s[nt].z = __expf(s[nt].z - mn1);
                s[nt].w = __expf(s[nt].w - mn1);
                sum0 += s[nt].x + s[nt].y;
                sum1 += s[nt].z + s[nt].w;
            }
            sum0 += __shfl_xor_sync(0xffffffffu, sum0, 1);
            sum0 += __shfl_xor_sync(0xffffffffu, sum0, 2);
            sum1 += __shfl_xor_sync(0xffffffffu, sum1, 1);
            sum1 += __shfl_xor_sync(0xffffffffu, sum1, 2);
            lrow[mt][0] = lrow[mt][0] * fac0 + sum0;
            lrow[mt][1] = lrow[mt][1] * fac1 + sum1;
            mrow[mt][0] = mn0; mrow[mt][1] = mn1;
#pragma unroll
            for (int dt = 0; dt < 8; dt++) {
                o[mt][dt].x *= fac0; o[mt][dt].y *= fac0;
                o[mt][dt].z *= fac1; o[mt][dt].w *= fac1;
            }

            // ---- store P (tf32, natural col order) ----
            {
                int pr = (mt * 64 + wm * 16 + g) * 72;
#pragma unroll
                for (int nt = 0; nt < 8; nt++) {
                    int c0 = nt * 8 + 2 * t4;
                    uint2 lo, hi;
                    lo.x = f2tf32(s[nt].x); lo.y = f2tf32(s[nt].y);
                    hi.x = f2tf32(s[nt].z); hi.y = f2tf32(s[nt].w);
                    *(uint2*)&Psm[pr + c0]          = lo;
                    *(uint2*)&Psm[pr + 8 * 72 + c0] = hi;
                }
            }
        }
        __syncwarp();   // P rows are private to this warp

        // ---- O += P V ----
#pragma unroll
        for (int ks = 0; ks < 8; ks++) {
            int kk = ks * 8 + t4;
            uint32_t pa[2][4];
#pragma unroll
            for (int mt = 0; mt < 2; mt++) {
                int pr = (mt * 64 + wm * 16 + g) * 72;
                pa[mt][0] = Psm[pr + kk];
                pa[mt][1] = Psm[pr + 8 * 72 + kk];
                pa[mt][2] = Psm[pr + kk + 4];
                pa[mt][3] = Psm[pr + 8 * 72 + kk + 4];
            }
#pragma unroll
            for (int dt = 0; dt < 8; dt++) {
                uint32_t b0 = Vt[kk * 72 + dt * 8 + g];
                uint32_t b1 = Vt[(kk + 4) * 72 + dt * 8 + g];
                if (act0) mma8(o[0][dt], pa[0], b0, b1, o[0][dt]);
                mma8(o[1][dt], pa[1], b0, b1, o[1][dt]);
            }
        }
        __syncthreads();
    }

    // ---- epilogue: normalize, store PERMUTED tf32 bits (feeds O-gemm) ----
#pragma unroll
    for (int mt = 0; mt < 2; mt++) {
        float inv0 = 1.0f / lrow[mt][0], inv1 = 1.0f / lrow[mt][1];
        int r1 = q0 + mt * 64 + wm * 16 + g;
        int r2 = r1 + 8;
        size_t ro1 = ((size_t)(b * T_SZ) + r1) * D_MODEL;
        size_t ro2 = ((size_t)(b * T_SZ) + r2) * D_MODEL;
#pragma unroll
        for (int dt = 0; dt < 8; dt++) {
            int c0 = h * 64 + dt * 8 + 2 * t4;
            int p0 = kperm(c0), p1 = kperm(c0 + 1);
            Og[ro1 + p0] = f2tf32(o[mt][dt].x * inv0);
            Og[ro1 + p1] = f2tf32(o[mt][dt].y * inv0);
            Og[ro2 + p0] = f2tf32(o[mt][dt].z * inv1);
            Og[ro2 + p1] = f2tf32(o[mt][dt].w * inv1);
        }
    }
}

// ---------------------------------------------------------------------------
extern "C" void kernel_launch(void* const* d_in, const int* in_sizes, int n_in,
                              void* d_out, int out_size)
{
    const float* x_q  = (const float*)d_in[0];
    const float* x_kv = (const float*)d_in[1];
    const float* Wq   = (const float*)d_in[2];
    const float* Wk   = (const float*)d_in[3];
    const float* Wv   = (const float*)d_in[4];
    const float* Wo   = (const float*)d_in[5];
    float* out = (float*)d_out;

    uint32_t *pxq, *pxkv, *pwq, *pwk, *pwv, *pwo, *pq, *pk, *pv, *pattn;
    cudaGetSymbolAddress((void**)&pxq,  g_xq);
    cudaGetSymbolAddress((void**)&pxkv, g_xkv);
    cudaGetSymbolAddress((void**)&pwq,  g_wq);
    cudaGetSymbolAddress((void**)&pwk,  g_wk);
    cudaGetSymbolAddress((void**)&pwv,  g_wv);
    cudaGetSymbolAddress((void**)&pwo,  g_wo);
    cudaGetSymbolAddress((void**)&pq,   g_q);
    cudaGetSymbolAddress((void**)&pk,   g_k);
    cudaGetSymbolAddress((void**)&pv,   g_v);
    cudaGetSymbolAddress((void**)&pattn, g_attn);

    const int ATTN_SMEM = (18432 + 128 * 72) * 4;   // 110592 B
    const int GEMM_SMEM = 4 * 5120 * 4;             // 81920 B
    cudaFuncSetAttribute(attn_tc_kernel,
                         cudaFuncAttributeMaxDynamicSharedMemorySize, ATTN_SMEM);
    cudaFuncSetAttribute(gemm_qkv_kernel,
                         cudaFuncAttributeMaxDynamicSharedMemorySize, GEMM_SMEM);
    cudaFuncSetAttribute(gemm_o_kernel,
                         cudaFuncAttributeMaxDynamicSharedMemorySize, GEMM_SMEM);

    // ---- pre-convert + k-permute inputs/weights ----
    const int NX8 = M_ROWS * D_MODEL / 8;     // 1M threads
    const int NW8 = D_MODEL * D_MODEL / 8;    // 128K threads
    cvtp_kernel<<<(NX8 + 255) / 256, 256>>>(x_q,  pxq,  NX8);
    cvtp_kernel<<<(NX8 + 255) / 256, 256>>>(x_kv, pxkv, NX8);
    cvtp_kernel<<<(NW8 + 255) / 256, 256>>>(Wq, pwq, NW8);
    cvtp_kernel<<<(NW8 + 255) / 256, 256>>>(Wk, pwk, NW8);
    cvtp_kernel<<<(NW8 + 255) / 256, 256>>>(Wv, pwv, NW8);
    cvtp_kernel<<<(NW8 + 255) / 256, 256>>>(Wo, pwo, NW8);

    // ---- fused Q/K/V projections ----
    gemm_qkv_kernel<<<dim3(D_MODEL / 128, M_ROWS / 128, 3), 256, GEMM_SMEM>>>();

    // ---- attention ----
    attn_tc_kernel<<<dim3(T_SZ / 128, NUM_HEADS, B_SZ), 128, ATTN_SMEM>>>(pq, pk, pv, pattn);

    // ---- output projection ----
    gemm_o_kernel<<<dim3(D_MODEL / 128, M_ROWS / 128), 256, GEMM_SMEM>>>(out);
}